// round 1
// baseline (speedup 1.0000x reference)
#include <cuda_runtime.h>
#include <math.h>

// Problem constants
#define BATCH  4
#define S_LEN  2048
#define NHEAD  12
#define DHEAD  100
#define HIDDEN 1200
#define M_TOT  (BATCH * S_LEN)          // 8192
#define BH     (BATCH * NHEAD)          // 48

// ---------------------------------------------------------------------------
// Scratch (static __device__ arrays: allocation-free per harness rules)
// Q,K,V stored as (b,h,s,d) contiguous. O stored the same way, which is
// EXACTLY the reference's raw reshape layout: per batch, (h,s,d) flat ==
// (s', 1200) flat because H*S*D == S*HIDDEN. So O is reused directly as the
// row-major A operand of the output projection.
// ---------------------------------------------------------------------------
__device__ float g_Q[BATCH * NHEAD * S_LEN * DHEAD];
__device__ float g_K[BATCH * NHEAD * S_LEN * DHEAD];
__device__ float g_V[BATCH * NHEAD * S_LEN * DHEAD];
__device__ float g_O[BATCH * NHEAD * S_LEN * DHEAD];

// ---------------------------------------------------------------------------
// GEMM_NT: C[m,n] = sum_k A[m,k] * B[n,k]
//   A: row-major (M_TOT, HIDDEN)   B: row-major (HIDDEN, HIDDEN) (= W, so C = A @ W^T)
// scatter == 1: write into (b,h,s,d) layout (for Q/K/V)
// scatter == 0: plain row-major C (M_TOT, HIDDEN) (for final output)
// Tiles: BM=BN=128, BK=16, 256 threads, 8x8 per-thread microtile.
// ---------------------------------------------------------------------------
__global__ __launch_bounds__(256) void gemm_nt_kernel(
    const float* __restrict__ A, const float* __restrict__ Bw,
    float* __restrict__ C, int scatter)
{
    __shared__ float As[16][128];
    __shared__ float Bs[16][128];

    const int tid = threadIdx.x;
    const int m0  = blockIdx.x * 128;
    const int n0  = blockIdx.y * 128;
    const int ty  = tid >> 4;      // 0..15 (row group)
    const int tx  = tid & 15;      // 0..15 (col group)

    float acc[8][8];
#pragma unroll
    for (int i = 0; i < 8; i++)
#pragma unroll
        for (int j = 0; j < 8; j++) acc[i][j] = 0.f;

    for (int k0 = 0; k0 < HIDDEN; k0 += 16) {
        // Cooperative loads: 512 float4 per operand tile, 2 per thread.
#pragma unroll
        for (int it = 0; it < 2; it++) {
            int id  = tid + it * 256;       // 0..511
            int row = id >> 2;              // 0..127
            int c4  = (id & 3) << 2;        // 0,4,8,12

            float4 va = *(const float4*)&A[(long)(m0 + row) * HIDDEN + k0 + c4];
            As[c4 + 0][row] = va.x; As[c4 + 1][row] = va.y;
            As[c4 + 2][row] = va.z; As[c4 + 3][row] = va.w;

            float4 vb = make_float4(0.f, 0.f, 0.f, 0.f);
            if (n0 + row < HIDDEN)
                vb = *(const float4*)&Bw[(long)(n0 + row) * HIDDEN + k0 + c4];
            Bs[c4 + 0][row] = vb.x; Bs[c4 + 1][row] = vb.y;
            Bs[c4 + 2][row] = vb.z; Bs[c4 + 3][row] = vb.w;
        }
        __syncthreads();

#pragma unroll
        for (int kk = 0; kk < 16; kk++) {
            float a[8], b[8];
            *(float4*)&a[0] = *(float4*)&As[kk][ty * 8];
            *(float4*)&a[4] = *(float4*)&As[kk][ty * 8 + 4];
            *(float4*)&b[0] = *(float4*)&Bs[kk][tx * 8];
            *(float4*)&b[4] = *(float4*)&Bs[kk][tx * 8 + 4];
#pragma unroll
            for (int i = 0; i < 8; i++)
#pragma unroll
                for (int j = 0; j < 8; j++)
                    acc[i][j] += a[i] * b[j];
        }
        __syncthreads();
    }

    // Epilogue
#pragma unroll
    for (int i = 0; i < 8; i++) {
        const int m  = m0 + ty * 8 + i;
        const int b_ = m >> 11;             // m / S_LEN
        const int s_ = m & (S_LEN - 1);
#pragma unroll
        for (int j = 0; j < 8; j++) {
            const int n = n0 + tx * 8 + j;
            if (n < HIDDEN) {
                if (scatter) {
                    const int h = n / DHEAD;
                    const int d = n % DHEAD;
                    C[(((long)b_ * NHEAD + h) * S_LEN + s_) * DHEAD + d] = acc[i][j];
                } else {
                    C[(long)m * HIDDEN + n] = acc[i][j];
                }
            }
        }
    }
}

// ---------------------------------------------------------------------------
// Flash attention (online softmax), fp32.
// Grid: (BH=48, S/64=32). Block: 256 threads.
// Per block: 64 query rows; loop over 32 kv tiles of 64 keys.
// logits = (q.k * sqrt(D) + alibi[t]) / (L+1) + mask[t]
// Thread layout 16x16: each thread owns score microtile rows ty*4..+3,
// cols tx*4..+3; O accum rows ty*4..+3, cols tx + 16*jj (jj<7, D padded 112).
// ---------------------------------------------------------------------------
#define QT_OFF   0            // Q^T [100][64]
#define KT_OFF   6400         // K^T [100][64]
#define VS_OFF   12800        // V   [64][112] (cols >=100 zero)
#define PT_OFF   19968        // P^T [64][68]  (kvcol-major)
#define BIAS_OFF 24320        // [64]
#define SMEM_FLOATS 24384
#define SMEM_BYTES  (SMEM_FLOATS * 4)

__global__ __launch_bounds__(256) void flash_kernel(
    const float* __restrict__ alibi, const float* __restrict__ mask,
    const int* __restrict__ layer_index,
    const float* __restrict__ Q, const float* __restrict__ K,
    const float* __restrict__ V, float* __restrict__ O)
{
    extern __shared__ float sm[];
    float* Qt   = sm + QT_OFF;
    float* Kt   = sm + KT_OFF;
    float* Vs   = sm + VS_OFF;
    float* Pt   = sm + PT_OFF;
    float* bias = sm + BIAS_OFF;

    const int tid = threadIdx.x;
    const int ty  = tid >> 4;
    const int tx  = tid & 15;
    const int bh  = blockIdx.x;           // 0..47
    const int q0  = blockIdx.y * 64;
    const int b_  = bh / NHEAD;

    const float inv = 1.f / (float)(layer_index[0] + 1);
    const float sc  = 10.f * inv;         // sqrt(100) / (L+1)

    // Load Q tile transposed: Qt[d][r]
    for (int id = tid; id < 64 * 25; id += 256) {
        const int r  = id / 25;
        const int d4 = (id % 25) * 4;
        float4 v = *(const float4*)&Q[((long)bh * S_LEN + q0 + r) * DHEAD + d4];
        Qt[(d4 + 0) * 64 + r] = v.x; Qt[(d4 + 1) * 64 + r] = v.y;
        Qt[(d4 + 2) * 64 + r] = v.z; Qt[(d4 + 3) * 64 + r] = v.w;
    }

    float mrow[4], lrow[4], acc[4][7];
#pragma unroll
    for (int i = 0; i < 4; i++) {
        mrow[i] = -1e30f; lrow[i] = 0.f;
#pragma unroll
        for (int j = 0; j < 7; j++) acc[i][j] = 0.f;
    }

    for (int kt = 0; kt < S_LEN / 64; kt++) {
        const int k0 = kt * 64;
        __syncthreads();   // protect Kt/Vs/bias from prior iteration readers

        // K tile transposed
        for (int id = tid; id < 64 * 25; id += 256) {
            const int r  = id / 25;
            const int d4 = (id % 25) * 4;
            float4 v = *(const float4*)&K[((long)bh * S_LEN + k0 + r) * DHEAD + d4];
            Kt[(d4 + 0) * 64 + r] = v.x; Kt[(d4 + 1) * 64 + r] = v.y;
            Kt[(d4 + 2) * 64 + r] = v.z; Kt[(d4 + 3) * 64 + r] = v.w;
        }
        // V tile, row-major padded to 112 cols (zero-fill pad)
        for (int id = tid; id < 64 * 28; id += 256) {
            const int r  = id / 28;
            const int c4 = (id % 28) * 4;
            float4 v = make_float4(0.f, 0.f, 0.f, 0.f);
            if (c4 < DHEAD)
                v = *(const float4*)&V[((long)bh * S_LEN + k0 + r) * DHEAD + c4];
            *(float4*)&Vs[r * 112 + c4] = v;
        }
        // per-key bias
        if (tid < 64) {
            const int t = k0 + tid;
            bias[tid] = alibi[(long)bh * S_LEN + t] * inv + mask[(long)b_ * S_LEN + t];
        }
        __syncthreads();

        // --- scores microtile ---
        float s_[4][4];
#pragma unroll
        for (int i = 0; i < 4; i++)
#pragma unroll
            for (int j = 0; j < 4; j++) s_[i][j] = 0.f;

#pragma unroll 4
        for (int k = 0; k < DHEAD; k++) {
            float4 a = *(float4*)&Qt[k * 64 + ty * 4];
            float4 bb = *(float4*)&Kt[k * 64 + tx * 4];
            const float av[4] = {a.x, a.y, a.z, a.w};
            const float bv[4] = {bb.x, bb.y, bb.z, bb.w};
#pragma unroll
            for (int i = 0; i < 4; i++)
#pragma unroll
                for (int j = 0; j < 4; j++)
                    s_[i][j] += av[i] * bv[j];
        }
#pragma unroll
        for (int i = 0; i < 4; i++)
#pragma unroll
            for (int j = 0; j < 4; j++)
                s_[i][j] = s_[i][j] * sc + bias[tx * 4 + j];

        // --- online softmax ---
#pragma unroll
        for (int i = 0; i < 4; i++) {
            float tm = fmaxf(fmaxf(s_[i][0], s_[i][1]), fmaxf(s_[i][2], s_[i][3]));
#pragma unroll
            for (int off = 8; off > 0; off >>= 1)
                tm = fmaxf(tm, __shfl_xor_sync(0xffffffffu, tm, off));
            const float mnew   = fmaxf(mrow[i], tm);
            const float factor = __expf(mrow[i] - mnew);
            float rs = 0.f;
#pragma unroll
            for (int j = 0; j < 4; j++) {
                s_[i][j] = __expf(s_[i][j] - mnew);
                rs += s_[i][j];
            }
#pragma unroll
            for (int off = 8; off > 0; off >>= 1)
                rs += __shfl_xor_sync(0xffffffffu, rs, off);
            lrow[i] = lrow[i] * factor + rs;
            mrow[i] = mnew;
#pragma unroll
            for (int jj = 0; jj < 7; jj++) acc[i][jj] *= factor;
        }

        // P^T to smem: Pt[kvcol][qrow]
#pragma unroll
        for (int i = 0; i < 4; i++)
#pragma unroll
            for (int j = 0; j < 4; j++)
                Pt[(tx * 4 + j) * 68 + (ty * 4 + i)] = s_[i][j];
        __syncthreads();

        // --- O += P @ V ---
#pragma unroll 2
        for (int k = 0; k < 64; k++) {
            float4 pv = *(float4*)&Pt[k * 68 + ty * 4];
#pragma unroll
            for (int jj = 0; jj < 7; jj++) {
                const float vv = Vs[k * 112 + tx + 16 * jj];
                acc[0][jj] += pv.x * vv;
                acc[1][jj] += pv.y * vv;
                acc[2][jj] += pv.z * vv;
                acc[3][jj] += pv.w * vv;
            }
        }
    }

    // Epilogue: normalize and store in (b,h,s,d) layout
#pragma unroll
    for (int i = 0; i < 4; i++) {
        const float il = 1.f / lrow[i];
        const long rowbase = ((long)bh * S_LEN + q0 + ty * 4 + i) * DHEAD;
#pragma unroll
        for (int jj = 0; jj < 7; jj++) {
            const int c = tx + 16 * jj;
            if (c < DHEAD) O[rowbase + c] = acc[i][jj] * il;
        }
    }
}

// ---------------------------------------------------------------------------
// Launch
// ---------------------------------------------------------------------------
extern "C" void kernel_launch(void* const* d_in, const int* in_sizes, int n_in,
                              void* d_out, int out_size)
{
    const float* x     = (const float*)d_in[0];
    const float* alibi = (const float*)d_in[1];
    const float* mask  = (const float*)d_in[2];
    const float* wq    = (const float*)d_in[3];
    const float* wk    = (const float*)d_in[4];
    const float* wv    = (const float*)d_in[5];
    const float* wo    = (const float*)d_in[6];
    const int*   li    = (const int*)d_in[7];
    float* out = (float*)d_out;

    float *Qp, *Kp, *Vp, *Op;
    cudaGetSymbolAddress((void**)&Qp, g_Q);
    cudaGetSymbolAddress((void**)&Kp, g_K);
    cudaGetSymbolAddress((void**)&Vp, g_V);
    cudaGetSymbolAddress((void**)&Op, g_O);

    cudaFuncSetAttribute(flash_kernel,
                         cudaFuncAttributeMaxDynamicSharedMemorySize, SMEM_BYTES);

    dim3 gg(M_TOT / 128, (HIDDEN + 127) / 128);   // (64, 10)
    gemm_nt_kernel<<<gg, 256>>>(x, wq, Qp, 1);
    gemm_nt_kernel<<<gg, 256>>>(x, wk, Kp, 1);
    gemm_nt_kernel<<<gg, 256>>>(x, wv, Vp, 1);

    flash_kernel<<<dim3(BH, S_LEN / 64), 256, SMEM_BYTES>>>(
        alibi, mask, li, Qp, Kp, Vp, Op);

    gemm_nt_kernel<<<gg, 256>>>(Op, wo, out, 0);
}

// round 2
// speedup vs baseline: 1.4926x; 1.4926x over previous
#include <cuda_runtime.h>
#include <math.h>

// Problem constants
#define BATCH  4
#define S_LEN  2048
#define NHEAD  12
#define DHEAD  100
#define HIDDEN 1200
#define M_TOT  (BATCH * S_LEN)          // 8192
#define BH     (BATCH * NHEAD)          // 48

// Scratch (b,h,s,d) contiguous. O layout == reference's raw reshape (H*S*D == S*HID).
__device__ float g_Q[BATCH * NHEAD * S_LEN * DHEAD];
__device__ float g_K[BATCH * NHEAD * S_LEN * DHEAD];
__device__ float g_V[BATCH * NHEAD * S_LEN * DHEAD];
__device__ float g_O[BATCH * NHEAD * S_LEN * DHEAD];

// ---------------------------------------------------------------------------
// TF32 split helpers + m16n8k8 mma
// ---------------------------------------------------------------------------
__device__ __forceinline__ void split_tf32(float x, unsigned& hi, unsigned& lo) {
    asm("cvt.rna.tf32.f32 %0, %1;" : "=r"(hi) : "f"(x));
    float r = x - __uint_as_float(hi);
    asm("cvt.rna.tf32.f32 %0, %1;" : "=r"(lo) : "f"(r));
}

__device__ __forceinline__ void mma8(float* c, const unsigned* a, const unsigned* b) {
    asm volatile(
        "mma.sync.aligned.m16n8k8.row.col.f32.tf32.tf32.f32 "
        "{%0,%1,%2,%3}, {%4,%5,%6,%7}, {%8,%9}, {%0,%1,%2,%3};\n"
        : "+f"(c[0]), "+f"(c[1]), "+f"(c[2]), "+f"(c[3])
        : "r"(a[0]), "r"(a[1]), "r"(a[2]), "r"(a[3]), "r"(b[0]), "r"(b[1]));
}

// ---------------------------------------------------------------------------
// GEMM_NT (tf32 split): C[m,n] = sum_k A[m,k] * W[n,k]
// BM=BN=128, BK=16, 256 threads, warp grid 2x4, warp tile 64x32.
// scatter==1 -> write (b,h,s,d); scatter==0 -> row-major (M, HIDDEN).
// ---------------------------------------------------------------------------
__global__ __launch_bounds__(256, 2) void gemm_tf32_kernel(
    const float* __restrict__ A, const float* __restrict__ Bw,
    float* __restrict__ C, int scatter)
{
    __shared__ float As[128][20];   // [m][k] stride 20 -> conflict-free frags
    __shared__ float Bs[128][20];   // [n][k]

    const int tid  = threadIdx.x;
    const int lane = tid & 31;
    const int warp = tid >> 5;
    const int wm   = warp >> 2;     // 0..1
    const int wn   = warp & 3;      // 0..3
    const int m0   = blockIdx.x * 128;
    const int n0   = blockIdx.y * 128;
    const int lr   = lane >> 2;     // 0..7
    const int lc   = lane & 3;      // 0..3

    float acc[4][4][4];
#pragma unroll
    for (int i = 0; i < 4; i++)
#pragma unroll
        for (int j = 0; j < 4; j++)
#pragma unroll
            for (int r = 0; r < 4; r++) acc[i][j][r] = 0.f;

    for (int k0 = 0; k0 < HIDDEN; k0 += 16) {
        __syncthreads();
#pragma unroll
        for (int it = 0; it < 2; it++) {
            const int idx = tid + it * 256;       // 0..511
            const int row = idx >> 2;             // 0..127
            const int c4  = (idx & 3) << 2;
            float4 va = *(const float4*)&A[(long)(m0 + row) * HIDDEN + k0 + c4];
            *(float4*)&As[row][c4] = va;
            float4 vb = make_float4(0.f, 0.f, 0.f, 0.f);
            if (n0 + row < HIDDEN)
                vb = *(const float4*)&Bw[(long)(n0 + row) * HIDDEN + k0 + c4];
            *(float4*)&Bs[row][c4] = vb;
        }
        __syncthreads();

#pragma unroll
        for (int ks = 0; ks < 16; ks += 8) {
            unsigned bh_[4][2], bl_[4][2];
#pragma unroll
            for (int nt = 0; nt < 4; nt++) {
                const int n = wn * 32 + nt * 8 + lr;
                split_tf32(Bs[n][ks + lc],     bh_[nt][0], bl_[nt][0]);
                split_tf32(Bs[n][ks + 4 + lc], bh_[nt][1], bl_[nt][1]);
            }
#pragma unroll
            for (int mt = 0; mt < 4; mt++) {
                const int m = wm * 64 + mt * 16 + lr;
                unsigned ah[4], al[4];
                split_tf32(As[m][ks + lc],         ah[0], al[0]);
                split_tf32(As[m + 8][ks + lc],     ah[1], al[1]);
                split_tf32(As[m][ks + 4 + lc],     ah[2], al[2]);
                split_tf32(As[m + 8][ks + 4 + lc], ah[3], al[3]);
#pragma unroll
                for (int nt = 0; nt < 4; nt++) {
                    mma8(acc[mt][nt], ah, bh_[nt]);
                    mma8(acc[mt][nt], ah, bl_[nt]);
                    mma8(acc[mt][nt], al, bh_[nt]);
                }
            }
        }
    }

    // Epilogue
#pragma unroll
    for (int mt = 0; mt < 4; mt++) {
#pragma unroll
        for (int nt = 0; nt < 4; nt++) {
            const int m = m0 + wm * 64 + mt * 16 + lr;
            const int n = n0 + wn * 32 + nt * 8 + lc * 2;
#pragma unroll
            for (int half = 0; half < 2; half++) {
                const int mm = m + half * 8;
                const int b_ = mm >> 11;
                const int s_ = mm & (S_LEN - 1);
#pragma unroll
                for (int cj = 0; cj < 2; cj++) {
                    const int nn = n + cj;
                    if (nn < HIDDEN) {
                        const float v = acc[mt][nt][half * 2 + cj];
                        if (scatter) {
                            const int h = nn / DHEAD;
                            const int d = nn % DHEAD;
                            C[(((long)b_ * NHEAD + h) * S_LEN + s_) * DHEAD + d] = v;
                        } else {
                            C[(long)mm * HIDDEN + nn] = v;
                        }
                    }
                }
            }
        }
    }
}

// ---------------------------------------------------------------------------
// Flash attention, tf32 split mma. Block = 128 threads (4 warps).
// Tile: 64 q rows (warp w -> rows 16w..16w+15), kv tiles of 64, D padded 104.
// smem (floats): Qs[64][108] Ks[64][108] Vs[64][108] Ps[64][68] bias[64]
// ---------------------------------------------------------------------------
#define QS_OFF   0
#define KS_OFF   6912
#define VS_OFF   13824
#define PS_OFF   20736
#define BIAS_OFF 25088
#define FL_SMEM_FLOATS 25152
#define FL_SMEM_BYTES  (FL_SMEM_FLOATS * 4)
#define NDT 13   // d n-tiles (104/8)

__global__ __launch_bounds__(128) void flash_kernel(
    const float* __restrict__ alibi, const float* __restrict__ mask,
    const int* __restrict__ layer_index,
    const float* __restrict__ Q, const float* __restrict__ K,
    const float* __restrict__ V, float* __restrict__ O)
{
    extern __shared__ float sm[];
    float* Qs   = sm + QS_OFF;
    float* Ks   = sm + KS_OFF;
    float* Vs   = sm + VS_OFF;
    float* Ps   = sm + PS_OFF;
    float* bias = sm + BIAS_OFF;

    const int tid  = threadIdx.x;
    const int lane = tid & 31;
    const int w    = tid >> 5;          // 0..3
    const int lr   = lane >> 2;         // 0..7
    const int lc   = lane & 3;          // 0..3
    const int bh   = blockIdx.x;        // 0..47
    const int q0   = blockIdx.y * 64;
    const int b_   = bh / NHEAD;

    const float inv = 1.f / (float)(layer_index[0] + 1);
    const float sc  = 10.f * inv;       // sqrt(100)/(L+1)

    // Load Q tile (rows q0..q0+63), cols 0..99
    for (int id = tid; id < 64 * 25; id += 128) {
        const int r  = id / 25;
        const int c4 = (id % 25) * 4;
        float4 v = *(const float4*)&Q[((long)bh * S_LEN + q0 + r) * DHEAD + c4];
        *(float4*)&Qs[r * 108 + c4] = v;
    }
    // Zero pad cols 100..107 of Qs/Ks/Vs (never overwritten afterwards)
    {
        const int r  = tid >> 1;
        const int c4 = 100 + (tid & 1) * 4;
        const float4 z = make_float4(0.f, 0.f, 0.f, 0.f);
        *(float4*)&Qs[r * 108 + c4] = z;
        *(float4*)&Ks[r * 108 + c4] = z;
        *(float4*)&Vs[r * 108 + c4] = z;
    }

    float oacc[NDT][4];
#pragma unroll
    for (int nt = 0; nt < NDT; nt++)
#pragma unroll
        for (int r = 0; r < 4; r++) oacc[nt][r] = 0.f;
    float mrow0 = -1e30f, mrow1 = -1e30f, lsum0 = 0.f, lsum1 = 0.f;

    for (int kt = 0; kt < S_LEN / 64; kt++) {
        const int k0g = kt * 64;
        __syncthreads();   // prior-iteration readers done before overwrite

        for (int id = tid; id < 64 * 25; id += 128) {
            const int r  = id / 25;
            const int c4 = (id % 25) * 4;
            float4 vk = *(const float4*)&K[((long)bh * S_LEN + k0g + r) * DHEAD + c4];
            *(float4*)&Ks[r * 108 + c4] = vk;
            float4 vv = *(const float4*)&V[((long)bh * S_LEN + k0g + r) * DHEAD + c4];
            *(float4*)&Vs[r * 108 + c4] = vv;
        }
        if (tid < 64) {
            const int t = k0g + tid;
            bias[tid] = alibi[(long)bh * S_LEN + t] * inv + mask[(long)b_ * S_LEN + t];
        }
        __syncthreads();

        // ---- S = Q K^T (rows 16w..16w+15, 64 cols) ----
        float sacc[8][4];
#pragma unroll
        for (int nt = 0; nt < 8; nt++)
#pragma unroll
            for (int r = 0; r < 4; r++) sacc[nt][r] = 0.f;

#pragma unroll
        for (int kc = 0; kc < 13; kc++) {
            const int k0 = kc * 8;
            const int ar = 16 * w + lr;
            unsigned ah[4], al[4];
            split_tf32(Qs[ar * 108 + k0 + lc],           ah[0], al[0]);
            split_tf32(Qs[(ar + 8) * 108 + k0 + lc],     ah[1], al[1]);
            split_tf32(Qs[ar * 108 + k0 + 4 + lc],       ah[2], al[2]);
            split_tf32(Qs[(ar + 8) * 108 + k0 + 4 + lc], ah[3], al[3]);
#pragma unroll
            for (int nt = 0; nt < 8; nt++) {
                const int bn = nt * 8 + lr;           // key index
                unsigned bh2[2], bl2[2];
                split_tf32(Ks[bn * 108 + k0 + lc],     bh2[0], bl2[0]);
                split_tf32(Ks[bn * 108 + k0 + 4 + lc], bh2[1], bl2[1]);
                mma8(sacc[nt], ah, bh2);
                mma8(sacc[nt], ah, bl2);
                mma8(sacc[nt], al, bh2);
            }
        }

        // ---- scale + bias ----
#pragma unroll
        for (int nt = 0; nt < 8; nt++) {
            const int col = nt * 8 + lc * 2;
            const float b0v = bias[col], b1v = bias[col + 1];
            sacc[nt][0] = sacc[nt][0] * sc + b0v;
            sacc[nt][1] = sacc[nt][1] * sc + b1v;
            sacc[nt][2] = sacc[nt][2] * sc + b0v;
            sacc[nt][3] = sacc[nt][3] * sc + b1v;
        }

        // ---- online softmax (rows r0 = 16w+lr, r1 = r0+8) ----
        float rm0 = -1e30f, rm1 = -1e30f;
#pragma unroll
        for (int nt = 0; nt < 8; nt++) {
            rm0 = fmaxf(rm0, fmaxf(sacc[nt][0], sacc[nt][1]));
            rm1 = fmaxf(rm1, fmaxf(sacc[nt][2], sacc[nt][3]));
        }
        rm0 = fmaxf(rm0, __shfl_xor_sync(0xffffffffu, rm0, 1));
        rm0 = fmaxf(rm0, __shfl_xor_sync(0xffffffffu, rm0, 2));
        rm1 = fmaxf(rm1, __shfl_xor_sync(0xffffffffu, rm1, 1));
        rm1 = fmaxf(rm1, __shfl_xor_sync(0xffffffffu, rm1, 2));
        const float mn0 = fmaxf(mrow0, rm0);
        const float mn1 = fmaxf(mrow1, rm1);
        const float f0  = __expf(mrow0 - mn0);
        const float f1  = __expf(mrow1 - mn1);
        float rs0 = 0.f, rs1 = 0.f;
#pragma unroll
        for (int nt = 0; nt < 8; nt++) {
            sacc[nt][0] = __expf(sacc[nt][0] - mn0);
            sacc[nt][1] = __expf(sacc[nt][1] - mn0);
            sacc[nt][2] = __expf(sacc[nt][2] - mn1);
            sacc[nt][3] = __expf(sacc[nt][3] - mn1);
            rs0 += sacc[nt][0] + sacc[nt][1];
            rs1 += sacc[nt][2] + sacc[nt][3];
        }
        rs0 += __shfl_xor_sync(0xffffffffu, rs0, 1);
        rs0 += __shfl_xor_sync(0xffffffffu, rs0, 2);
        rs1 += __shfl_xor_sync(0xffffffffu, rs1, 1);
        rs1 += __shfl_xor_sync(0xffffffffu, rs1, 2);
        lsum0 = lsum0 * f0 + rs0;
        lsum1 = lsum1 * f1 + rs1;
        mrow0 = mn0;
        mrow1 = mn1;
#pragma unroll
        for (int nt = 0; nt < NDT; nt++) {
            oacc[nt][0] *= f0; oacc[nt][1] *= f0;
            oacc[nt][2] *= f1; oacc[nt][3] *= f1;
        }

        // ---- write P (own-warp rows only) ----
        {
            const int pr = 16 * w + lr;
#pragma unroll
            for (int nt = 0; nt < 8; nt++) {
                const int col = nt * 8 + lc * 2;
                Ps[pr * 68 + col]           = sacc[nt][0];
                Ps[pr * 68 + col + 1]       = sacc[nt][1];
                Ps[(pr + 8) * 68 + col]     = sacc[nt][2];
                Ps[(pr + 8) * 68 + col + 1] = sacc[nt][3];
            }
        }
        __syncwarp();

        // ---- O += P V ----
#pragma unroll
        for (int ks = 0; ks < 8; ks++) {
            const int k0 = ks * 8;
            const int ar = 16 * w + lr;
            unsigned pah[4], pal[4];
            split_tf32(Ps[ar * 68 + k0 + lc],           pah[0], pal[0]);
            split_tf32(Ps[(ar + 8) * 68 + k0 + lc],     pah[1], pal[1]);
            split_tf32(Ps[ar * 68 + k0 + 4 + lc],       pah[2], pal[2]);
            split_tf32(Ps[(ar + 8) * 68 + k0 + 4 + lc], pah[3], pal[3]);
#pragma unroll
            for (int nt = 0; nt < NDT; nt++) {
                const int bn = nt * 8 + lr;     // d index
                unsigned bh2[2], bl2[2];
                split_tf32(Vs[(k0 + lc) * 108 + bn],     bh2[0], bl2[0]);
                split_tf32(Vs[(k0 + 4 + lc) * 108 + bn], bh2[1], bl2[1]);
                mma8(oacc[nt], pah, bh2);
                mma8(oacc[nt], pah, bl2);
                mma8(oacc[nt], pal, bh2);
            }
        }
    }

    // ---- normalize + store (b,h,s,d) ----
    const float il0 = 1.f / lsum0;
    const float il1 = 1.f / lsum1;
    const int r0 = q0 + 16 * w + lr;
    const long base0 = ((long)bh * S_LEN + r0) * DHEAD;
    const long base1 = ((long)bh * S_LEN + r0 + 8) * DHEAD;
#pragma unroll
    for (int nt = 0; nt < NDT; nt++) {
        const int col = nt * 8 + lc * 2;
        if (col < DHEAD) {
            O[base0 + col] = oacc[nt][0] * il0;
            O[base1 + col] = oacc[nt][2] * il1;
        }
        if (col + 1 < DHEAD) {
            O[base0 + col + 1] = oacc[nt][1] * il0;
            O[base1 + col + 1] = oacc[nt][3] * il1;
        }
    }
}

// ---------------------------------------------------------------------------
// Launch
// ---------------------------------------------------------------------------
extern "C" void kernel_launch(void* const* d_in, const int* in_sizes, int n_in,
                              void* d_out, int out_size)
{
    const float* x     = (const float*)d_in[0];
    const float* alibi = (const float*)d_in[1];
    const float* mask  = (const float*)d_in[2];
    const float* wq    = (const float*)d_in[3];
    const float* wk    = (const float*)d_in[4];
    const float* wv    = (const float*)d_in[5];
    const float* wo    = (const float*)d_in[6];
    const int*   li    = (const int*)d_in[7];
    float* out = (float*)d_out;

    float *Qp, *Kp, *Vp, *Op;
    cudaGetSymbolAddress((void**)&Qp, g_Q);
    cudaGetSymbolAddress((void**)&Kp, g_K);
    cudaGetSymbolAddress((void**)&Vp, g_V);
    cudaGetSymbolAddress((void**)&Op, g_O);

    cudaFuncSetAttribute(flash_kernel,
                         cudaFuncAttributeMaxDynamicSharedMemorySize, FL_SMEM_BYTES);

    dim3 gg(M_TOT / 128, (HIDDEN + 127) / 128);   // (64, 10)
    gemm_tf32_kernel<<<gg, 256>>>(x, wq, Qp, 1);
    gemm_tf32_kernel<<<gg, 256>>>(x, wk, Kp, 1);
    gemm_tf32_kernel<<<gg, 256>>>(x, wv, Vp, 1);

    flash_kernel<<<dim3(BH, S_LEN / 64), 128, FL_SMEM_BYTES>>>(
        alibi, mask, li, Qp, Kp, Vp, Op);

    gemm_tf32_kernel<<<gg, 256>>>(Op, wo, out, 0);
}

// round 3
// speedup vs baseline: 1.5680x; 1.0505x over previous
#include <cuda_runtime.h>
#include <math.h>

// Problem constants
#define BATCH  4
#define S_LEN  2048
#define NHEAD  12
#define DHEAD  100
#define HIDDEN 1200
#define M_TOT  (BATCH * S_LEN)          // 8192
#define BH     (BATCH * NHEAD)          // 48

// Scratch (b,h,s,d) contiguous. O layout == reference's raw reshape (H*S*D == S*HID).
__device__ float g_Q[BATCH * NHEAD * S_LEN * DHEAD];
__device__ float g_K[BATCH * NHEAD * S_LEN * DHEAD];
__device__ float g_V[BATCH * NHEAD * S_LEN * DHEAD];
__device__ float g_O[BATCH * NHEAD * S_LEN * DHEAD];

// ---------------------------------------------------------------------------
// TF32 split helpers + m16n8k8 mma
// ---------------------------------------------------------------------------
__device__ __forceinline__ void split_tf32(float x, unsigned& hi, unsigned& lo) {
    asm("cvt.rna.tf32.f32 %0, %1;" : "=r"(hi) : "f"(x));
    float r = x - __uint_as_float(hi);
    asm("cvt.rna.tf32.f32 %0, %1;" : "=r"(lo) : "f"(r));
}

__device__ __forceinline__ void mma8(float* c, const unsigned* a, const unsigned* b) {
    asm volatile(
        "mma.sync.aligned.m16n8k8.row.col.f32.tf32.tf32.f32 "
        "{%0,%1,%2,%3}, {%4,%5,%6,%7}, {%8,%9}, {%0,%1,%2,%3};\n"
        : "+f"(c[0]), "+f"(c[1]), "+f"(c[2]), "+f"(c[3])
        : "r"(a[0]), "r"(a[1]), "r"(a[2]), "r"(a[3]), "r"(b[0]), "r"(b[1]));
}

// ---------------------------------------------------------------------------
// GEMM_NT (tf32 split, operands pre-split in smem, reg-double-buffered loads)
// C[m,n] = sum_k A[m,k] * W[n,k].  BM=BN=128, BK=16, 256 threads.
// scatter==1 -> write (b,h,s,d); scatter==0 -> row-major (M, HIDDEN).
// ---------------------------------------------------------------------------
__global__ __launch_bounds__(256, 2) void gemm_tf32_kernel(
    const float* __restrict__ A, const float* __restrict__ Bw,
    float* __restrict__ C, int scatter)
{
    __shared__ float Ahi[128][20], Alo[128][20];
    __shared__ float Bhi[128][20], Blo[128][20];

    const int tid  = threadIdx.x;
    const int lane = tid & 31;
    const int warp = tid >> 5;
    const int wm   = warp >> 2;     // 0..1
    const int wn   = warp & 3;      // 0..3
    const int m0   = blockIdx.x * 128;
    const int n0   = blockIdx.y * 128;
    const int lr   = lane >> 2;     // 0..7
    const int lc   = lane & 3;      // 0..3

    float acc[4][4][4];
#pragma unroll
    for (int i = 0; i < 4; i++)
#pragma unroll
        for (int j = 0; j < 4; j++)
#pragma unroll
            for (int r = 0; r < 4; r++) acc[i][j][r] = 0.f;

    float4 pa[2], pb[2];
    // preload first k-tile
#pragma unroll
    for (int it = 0; it < 2; it++) {
        const int idx = tid + it * 256;
        const int row = idx >> 2;
        const int c4  = (idx & 3) << 2;
        pa[it] = *(const float4*)&A[(long)(m0 + row) * HIDDEN + c4];
        pb[it] = make_float4(0.f, 0.f, 0.f, 0.f);
        if (n0 + row < HIDDEN)
            pb[it] = *(const float4*)&Bw[(long)(n0 + row) * HIDDEN + c4];
    }

    for (int k0 = 0; k0 < HIDDEN; k0 += 16) {
        // store + split current tile
#pragma unroll
        for (int it = 0; it < 2; it++) {
            const int idx = tid + it * 256;
            const int row = idx >> 2;
            const int c4  = (idx & 3) << 2;
            unsigned h0, l0, h1, l1, h2, l2, h3, l3;
            split_tf32(pa[it].x, h0, l0); split_tf32(pa[it].y, h1, l1);
            split_tf32(pa[it].z, h2, l2); split_tf32(pa[it].w, h3, l3);
            *(float4*)&Ahi[row][c4] = make_float4(__uint_as_float(h0), __uint_as_float(h1),
                                                  __uint_as_float(h2), __uint_as_float(h3));
            *(float4*)&Alo[row][c4] = make_float4(__uint_as_float(l0), __uint_as_float(l1),
                                                  __uint_as_float(l2), __uint_as_float(l3));
            split_tf32(pb[it].x, h0, l0); split_tf32(pb[it].y, h1, l1);
            split_tf32(pb[it].z, h2, l2); split_tf32(pb[it].w, h3, l3);
            *(float4*)&Bhi[row][c4] = make_float4(__uint_as_float(h0), __uint_as_float(h1),
                                                  __uint_as_float(h2), __uint_as_float(h3));
            *(float4*)&Blo[row][c4] = make_float4(__uint_as_float(l0), __uint_as_float(l1),
                                                  __uint_as_float(l2), __uint_as_float(l3));
        }
        __syncthreads();

        // prefetch next tile (overlaps with mma below)
        if (k0 + 16 < HIDDEN) {
#pragma unroll
            for (int it = 0; it < 2; it++) {
                const int idx = tid + it * 256;
                const int row = idx >> 2;
                const int c4  = (idx & 3) << 2;
                pa[it] = *(const float4*)&A[(long)(m0 + row) * HIDDEN + k0 + 16 + c4];
                pb[it] = make_float4(0.f, 0.f, 0.f, 0.f);
                if (n0 + row < HIDDEN)
                    pb[it] = *(const float4*)&Bw[(long)(n0 + row) * HIDDEN + k0 + 16 + c4];
            }
        }

#pragma unroll
        for (int ks = 0; ks < 16; ks += 8) {
            unsigned bh_[4][2], bl_[4][2];
#pragma unroll
            for (int nt = 0; nt < 4; nt++) {
                const int n = wn * 32 + nt * 8 + lr;
                bh_[nt][0] = __float_as_uint(Bhi[n][ks + lc]);
                bh_[nt][1] = __float_as_uint(Bhi[n][ks + 4 + lc]);
                bl_[nt][0] = __float_as_uint(Blo[n][ks + lc]);
                bl_[nt][1] = __float_as_uint(Blo[n][ks + 4 + lc]);
            }
#pragma unroll
            for (int mt = 0; mt < 4; mt++) {
                const int m = wm * 64 + mt * 16 + lr;
                unsigned ah[4], al[4];
                ah[0] = __float_as_uint(Ahi[m][ks + lc]);
                ah[1] = __float_as_uint(Ahi[m + 8][ks + lc]);
                ah[2] = __float_as_uint(Ahi[m][ks + 4 + lc]);
                ah[3] = __float_as_uint(Ahi[m + 8][ks + 4 + lc]);
                al[0] = __float_as_uint(Alo[m][ks + lc]);
                al[1] = __float_as_uint(Alo[m + 8][ks + lc]);
                al[2] = __float_as_uint(Alo[m][ks + 4 + lc]);
                al[3] = __float_as_uint(Alo[m + 8][ks + 4 + lc]);
#pragma unroll
                for (int nt = 0; nt < 4; nt++) {
                    mma8(acc[mt][nt], ah, bh_[nt]);
                    mma8(acc[mt][nt], ah, bl_[nt]);
                    mma8(acc[mt][nt], al, bh_[nt]);
                }
            }
        }
        __syncthreads();
    }

    // Epilogue
#pragma unroll
    for (int mt = 0; mt < 4; mt++) {
#pragma unroll
        for (int nt = 0; nt < 4; nt++) {
            const int m = m0 + wm * 64 + mt * 16 + lr;
            const int n = n0 + wn * 32 + nt * 8 + lc * 2;
#pragma unroll
            for (int half = 0; half < 2; half++) {
                const int mm = m + half * 8;
                const int b_ = mm >> 11;
                const int s_ = mm & (S_LEN - 1);
#pragma unroll
                for (int cj = 0; cj < 2; cj++) {
                    const int nn = n + cj;
                    if (nn < HIDDEN) {
                        const float v = acc[mt][nt][half * 2 + cj];
                        if (scatter) {
                            const int h = nn / DHEAD;
                            const int d = nn % DHEAD;
                            C[(((long)b_ * NHEAD + h) * S_LEN + s_) * DHEAD + d] = v;
                        } else {
                            C[(long)mm * HIDDEN + nn] = v;
                        }
                    }
                }
            }
        }
    }
}

// ---------------------------------------------------------------------------
// Flash attention, tf32 split mma. 256 threads (8 warps), q-tile 128, kv 64.
// K/V pre-split into hi/lo smem (amortized over 8 warps); Q plain smem
// (split at read); P plain smem (split at read).
// smem floats: Qs[128][108], Khi/Klo/Vhi/Vlo[64][108], Ps[128][68], bias[64]
// ---------------------------------------------------------------------------
#define FST 108
#define QS_OFF   0                         // 128*108 = 13824
#define KHI_OFF  13824
#define KLO_OFF  20736
#define VHI_OFF  27648
#define VLO_OFF  34560
#define PS_OFF   41472                     // 128*68 = 8704
#define BIAS_OFF 50176
#define FL_SMEM_FLOATS 50240
#define FL_SMEM_BYTES  (FL_SMEM_FLOATS * 4)
#define NDT 13   // d n-tiles (104/8)

__global__ __launch_bounds__(256, 1) void flash_kernel(
    const float* __restrict__ alibi, const float* __restrict__ mask,
    const int* __restrict__ layer_index,
    const float* __restrict__ Q, const float* __restrict__ K,
    const float* __restrict__ V, float* __restrict__ O)
{
    extern __shared__ float sm[];
    float* Qs   = sm + QS_OFF;
    float* Khi  = sm + KHI_OFF;
    float* Klo  = sm + KLO_OFF;
    float* Vhi  = sm + VHI_OFF;
    float* Vlo  = sm + VLO_OFF;
    float* Ps   = sm + PS_OFF;
    float* bias = sm + BIAS_OFF;

    const int tid  = threadIdx.x;
    const int lane = tid & 31;
    const int w    = tid >> 5;          // 0..7
    const int lr   = lane >> 2;         // 0..7
    const int lc   = lane & 3;          // 0..3
    const int bh   = blockIdx.x;        // 0..47
    const int q0   = blockIdx.y * 128;
    const int b_   = bh / NHEAD;

    const float inv = 1.f / (float)(layer_index[0] + 1);
    const float sc  = 10.f * inv;       // sqrt(100)/(L+1)

    // Zero pad cols 100..107 (only written once; K/V split loop writes cols<100)
    {
        const float4 z = make_float4(0.f, 0.f, 0.f, 0.f);
        const int r  = tid >> 1;                 // 0..127
        const int c4 = 100 + (tid & 1) * 4;
        *(float4*)&Qs[r * FST + c4] = z;
        if (tid < 128) {
            const int r2 = tid >> 1;             // 0..63
            *(float4*)&Khi[r2 * FST + c4] = z;
            *(float4*)&Klo[r2 * FST + c4] = z;
            *(float4*)&Vhi[r2 * FST + c4] = z;
            *(float4*)&Vlo[r2 * FST + c4] = z;
        }
    }
    // Load Q tile (128 rows x 100)
    for (int id = tid; id < 128 * 25; id += 256) {
        const int r  = id / 25;
        const int c4 = (id % 25) * 4;
        *(float4*)&Qs[r * FST + c4] =
            *(const float4*)&Q[((long)bh * S_LEN + q0 + r) * DHEAD + c4];
    }

    float oacc[NDT][4];
#pragma unroll
    for (int nt = 0; nt < NDT; nt++)
#pragma unroll
        for (int r = 0; r < 4; r++) oacc[nt][r] = 0.f;
    float mrow0 = -1e30f, mrow1 = -1e30f, lsum0 = 0.f, lsum1 = 0.f;

    const int ar = 16 * w + lr;   // this thread's first q-row (local)

    for (int kt = 0; kt < S_LEN / 64; kt++) {
        const int k0g = kt * 64;
        __syncthreads();   // prior-iteration readers done before overwrite

        // Load + pre-split K and V tiles
        for (int id = tid; id < 64 * 25; id += 256) {
            const int r  = id / 25;
            const int c4 = (id % 25) * 4;
            unsigned h0, l0, h1, l1, h2, l2, h3, l3;
            float4 vk = *(const float4*)&K[((long)bh * S_LEN + k0g + r) * DHEAD + c4];
            split_tf32(vk.x, h0, l0); split_tf32(vk.y, h1, l1);
            split_tf32(vk.z, h2, l2); split_tf32(vk.w, h3, l3);
            *(float4*)&Khi[r * FST + c4] = make_float4(__uint_as_float(h0), __uint_as_float(h1),
                                                       __uint_as_float(h2), __uint_as_float(h3));
            *(float4*)&Klo[r * FST + c4] = make_float4(__uint_as_float(l0), __uint_as_float(l1),
                                                       __uint_as_float(l2), __uint_as_float(l3));
            float4 vv = *(const float4*)&V[((long)bh * S_LEN + k0g + r) * DHEAD + c4];
            split_tf32(vv.x, h0, l0); split_tf32(vv.y, h1, l1);
            split_tf32(vv.z, h2, l2); split_tf32(vv.w, h3, l3);
            *(float4*)&Vhi[r * FST + c4] = make_float4(__uint_as_float(h0), __uint_as_float(h1),
                                                       __uint_as_float(h2), __uint_as_float(h3));
            *(float4*)&Vlo[r * FST + c4] = make_float4(__uint_as_float(l0), __uint_as_float(l1),
                                                       __uint_as_float(l2), __uint_as_float(l3));
        }
        if (tid < 64) {
            const int t = k0g + tid;
            bias[tid] = alibi[(long)bh * S_LEN + t] * inv + mask[(long)b_ * S_LEN + t];
        }
        __syncthreads();

        // ---- S = Q K^T (warp rows 16w..16w+15, 64 cols) ----
        float sacc[8][4];
#pragma unroll
        for (int nt = 0; nt < 8; nt++)
#pragma unroll
            for (int r = 0; r < 4; r++) sacc[nt][r] = 0.f;

#pragma unroll
        for (int kc = 0; kc < 13; kc++) {
            const int k0 = kc * 8;
            unsigned ah[4], al[4];
            split_tf32(Qs[ar * FST + k0 + lc],           ah[0], al[0]);
            split_tf32(Qs[(ar + 8) * FST + k0 + lc],     ah[1], al[1]);
            split_tf32(Qs[ar * FST + k0 + 4 + lc],       ah[2], al[2]);
            split_tf32(Qs[(ar + 8) * FST + k0 + 4 + lc], ah[3], al[3]);
#pragma unroll
            for (int nt = 0; nt < 8; nt++) {
                const int bn = nt * 8 + lr;
                unsigned bh2[2], bl2[2];
                bh2[0] = __float_as_uint(Khi[bn * FST + k0 + lc]);
                bh2[1] = __float_as_uint(Khi[bn * FST + k0 + 4 + lc]);
                bl2[0] = __float_as_uint(Klo[bn * FST + k0 + lc]);
                bl2[1] = __float_as_uint(Klo[bn * FST + k0 + 4 + lc]);
                mma8(sacc[nt], ah, bh2);
                mma8(sacc[nt], ah, bl2);
                mma8(sacc[nt], al, bh2);
            }
        }

        // ---- scale + bias ----
#pragma unroll
        for (int nt = 0; nt < 8; nt++) {
            const int col = nt * 8 + lc * 2;
            const float b0v = bias[col], b1v = bias[col + 1];
            sacc[nt][0] = sacc[nt][0] * sc + b0v;
            sacc[nt][1] = sacc[nt][1] * sc + b1v;
            sacc[nt][2] = sacc[nt][2] * sc + b0v;
            sacc[nt][3] = sacc[nt][3] * sc + b1v;
        }

        // ---- online softmax ----
        float rm0 = -1e30f, rm1 = -1e30f;
#pragma unroll
        for (int nt = 0; nt < 8; nt++) {
            rm0 = fmaxf(rm0, fmaxf(sacc[nt][0], sacc[nt][1]));
            rm1 = fmaxf(rm1, fmaxf(sacc[nt][2], sacc[nt][3]));
        }
        rm0 = fmaxf(rm0, __shfl_xor_sync(0xffffffffu, rm0, 1));
        rm0 = fmaxf(rm0, __shfl_xor_sync(0xffffffffu, rm0, 2));
        rm1 = fmaxf(rm1, __shfl_xor_sync(0xffffffffu, rm1, 1));
        rm1 = fmaxf(rm1, __shfl_xor_sync(0xffffffffu, rm1, 2));
        const float mn0 = fmaxf(mrow0, rm0);
        const float mn1 = fmaxf(mrow1, rm1);
        const float f0  = __expf(mrow0 - mn0);
        const float f1  = __expf(mrow1 - mn1);
        float rs0 = 0.f, rs1 = 0.f;
#pragma unroll
        for (int nt = 0; nt < 8; nt++) {
            sacc[nt][0] = __expf(sacc[nt][0] - mn0);
            sacc[nt][1] = __expf(sacc[nt][1] - mn0);
            sacc[nt][2] = __expf(sacc[nt][2] - mn1);
            sacc[nt][3] = __expf(sacc[nt][3] - mn1);
            rs0 += sacc[nt][0] + sacc[nt][1];
            rs1 += sacc[nt][2] + sacc[nt][3];
        }
        rs0 += __shfl_xor_sync(0xffffffffu, rs0, 1);
        rs0 += __shfl_xor_sync(0xffffffffu, rs0, 2);
        rs1 += __shfl_xor_sync(0xffffffffu, rs1, 1);
        rs1 += __shfl_xor_sync(0xffffffffu, rs1, 2);
        lsum0 = lsum0 * f0 + rs0;
        lsum1 = lsum1 * f1 + rs1;
        mrow0 = mn0;
        mrow1 = mn1;
#pragma unroll
        for (int nt = 0; nt < NDT; nt++) {
            oacc[nt][0] *= f0; oacc[nt][1] *= f0;
            oacc[nt][2] *= f1; oacc[nt][3] *= f1;
        }

        // ---- write P (own-warp rows only) ----
#pragma unroll
        for (int nt = 0; nt < 8; nt++) {
            const int col = nt * 8 + lc * 2;
            Ps[ar * 68 + col]           = sacc[nt][0];
            Ps[ar * 68 + col + 1]       = sacc[nt][1];
            Ps[(ar + 8) * 68 + col]     = sacc[nt][2];
            Ps[(ar + 8) * 68 + col + 1] = sacc[nt][3];
        }
        __syncwarp();

        // ---- O += P V ----
#pragma unroll
        for (int ks = 0; ks < 8; ks++) {
            const int k0 = ks * 8;
            unsigned pah[4], pal[4];
            split_tf32(Ps[ar * 68 + k0 + lc],           pah[0], pal[0]);
            split_tf32(Ps[(ar + 8) * 68 + k0 + lc],     pah[1], pal[1]);
            split_tf32(Ps[ar * 68 + k0 + 4 + lc],       pah[2], pal[2]);
            split_tf32(Ps[(ar + 8) * 68 + k0 + 4 + lc], pah[3], pal[3]);
#pragma unroll
            for (int nt = 0; nt < NDT; nt++) {
                const int bn = nt * 8 + lr;     // d index
                unsigned bh2[2], bl2[2];
                bh2[0] = __float_as_uint(Vhi[(k0 + lc) * FST + bn]);
                bh2[1] = __float_as_uint(Vhi[(k0 + 4 + lc) * FST + bn]);
                bl2[0] = __float_as_uint(Vlo[(k0 + lc) * FST + bn]);
                bl2[1] = __float_as_uint(Vlo[(k0 + 4 + lc) * FST + bn]);
                mma8(oacc[nt], pah, bh2);
                mma8(oacc[nt], pah, bl2);
                mma8(oacc[nt], pal, bh2);
            }
        }
    }

    // ---- normalize + store (b,h,s,d) ----
    const float il0 = 1.f / lsum0;
    const float il1 = 1.f / lsum1;
    const int r0 = q0 + ar;
    const long base0 = ((long)bh * S_LEN + r0) * DHEAD;
    const long base1 = ((long)bh * S_LEN + r0 + 8) * DHEAD;
#pragma unroll
    for (int nt = 0; nt < NDT; nt++) {
        const int col = nt * 8 + lc * 2;
        if (col < DHEAD) {
            O[base0 + col] = oacc[nt][0] * il0;
            O[base1 + col] = oacc[nt][2] * il1;
        }
        if (col + 1 < DHEAD) {
            O[base0 + col + 1] = oacc[nt][1] * il0;
            O[base1 + col + 1] = oacc[nt][3] * il1;
        }
    }
}

// ---------------------------------------------------------------------------
// Launch
// ---------------------------------------------------------------------------
extern "C" void kernel_launch(void* const* d_in, const int* in_sizes, int n_in,
                              void* d_out, int out_size)
{
    const float* x     = (const float*)d_in[0];
    const float* alibi = (const float*)d_in[1];
    const float* mask  = (const float*)d_in[2];
    const float* wq    = (const float*)d_in[3];
    const float* wk    = (const float*)d_in[4];
    const float* wv    = (const float*)d_in[5];
    const float* wo    = (const float*)d_in[6];
    const int*   li    = (const int*)d_in[7];
    float* out = (float*)d_out;

    float *Qp, *Kp, *Vp, *Op;
    cudaGetSymbolAddress((void**)&Qp, g_Q);
    cudaGetSymbolAddress((void**)&Kp, g_K);
    cudaGetSymbolAddress((void**)&Vp, g_V);
    cudaGetSymbolAddress((void**)&Op, g_O);

    cudaFuncSetAttribute(flash_kernel,
                         cudaFuncAttributeMaxDynamicSharedMemorySize, FL_SMEM_BYTES);

    dim3 gg(M_TOT / 128, (HIDDEN + 127) / 128);   // (64, 10)
    gemm_tf32_kernel<<<gg, 256>>>(x, wq, Qp, 1);
    gemm_tf32_kernel<<<gg, 256>>>(x, wk, Kp, 1);
    gemm_tf32_kernel<<<gg, 256>>>(x, wv, Vp, 1);

    flash_kernel<<<dim3(BH, S_LEN / 128), 256, FL_SMEM_BYTES>>>(
        alibi, mask, li, Qp, Kp, Vp, Op);

    gemm_tf32_kernel<<<gg, 256>>>(Op, wo, out, 0);
}

// round 4
// speedup vs baseline: 2.5814x; 1.6463x over previous
#include <cuda_runtime.h>
#include <math.h>

// Problem constants
#define BATCH  4
#define S_LEN  2048
#define NHEAD  12
#define DHEAD  100
#define HIDDEN 1200
#define M_TOT  (BATCH * S_LEN)          // 8192
#define BH     (BATCH * NHEAD)          // 48

// Scratch. Q,K,O in (b,h,s,d). V in (b,h,d,s) (transposed for flash).
__device__ float g_Q[BATCH * NHEAD * S_LEN * DHEAD];
__device__ float g_K[BATCH * NHEAD * S_LEN * DHEAD];
__device__ float g_V[BATCH * NHEAD * S_LEN * DHEAD];
__device__ float g_O[BATCH * NHEAD * S_LEN * DHEAD];

// ---------------------------------------------------------------------------
// BF16 split helpers + mma
// cvt2(even, odd): packed bf16x2, low half = even-k element, high = odd-k.
// ---------------------------------------------------------------------------
__device__ __forceinline__ unsigned cvt2(float even, float odd) {
    unsigned r;
    asm("cvt.rn.bf16x2.f32 %0, %1, %2;" : "=r"(r) : "f"(odd), "f"(even));
    return r;
}
__device__ __forceinline__ float bf_lo(unsigned p) { return __uint_as_float(p << 16); }
__device__ __forceinline__ float bf_hi(unsigned p) { return __uint_as_float(p & 0xFFFF0000u); }

// split a pair (even, odd) into hi-packed and lo-packed bf16x2
__device__ __forceinline__ void split2(float e, float o, unsigned& h, unsigned& l) {
    h = cvt2(e, o);
    l = cvt2(e - bf_lo(h), o - bf_hi(h));
}

__device__ __forceinline__ void mma16(float* c, const unsigned* a, const unsigned* b) {
    asm volatile(
        "mma.sync.aligned.m16n8k16.row.col.f32.bf16.bf16.f32 "
        "{%0,%1,%2,%3}, {%4,%5,%6,%7}, {%8,%9}, {%0,%1,%2,%3};\n"
        : "+f"(c[0]), "+f"(c[1]), "+f"(c[2]), "+f"(c[3])
        : "r"(a[0]), "r"(a[1]), "r"(a[2]), "r"(a[3]), "r"(b[0]), "r"(b[1]));
}
__device__ __forceinline__ void mma8b(float* c, const unsigned* a, unsigned b) {
    asm volatile(
        "mma.sync.aligned.m16n8k8.row.col.f32.bf16.bf16.f32 "
        "{%0,%1,%2,%3}, {%4,%5}, {%6}, {%0,%1,%2,%3};\n"
        : "+f"(c[0]), "+f"(c[1]), "+f"(c[2]), "+f"(c[3])
        : "r"(a[0]), "r"(a[1]), "r"(b));
}

// ---------------------------------------------------------------------------
// GEMM_NT (bf16 3-mma split): C[m,n] = sum_k A[m,k] * W[n,k]
// BM=BN=128, BK=32 (38 tiles, zero-padded tail), 256 threads, warp tile 64x32.
// scatter: 0 -> row-major (M,HIDDEN); 1 -> (b,h,s,d); 2 -> (b,h,d,s).
// smem: packed bf16x2 (u32), 16 used cols, stride 20 (conflict-free).
// ---------------------------------------------------------------------------
#define GST 20

__global__ __launch_bounds__(256, 2) void gemm_bf16_kernel(
    const float* __restrict__ A, const float* __restrict__ Bw,
    float* __restrict__ C, int scatter)
{
    __shared__ unsigned Ahi[128][GST], Alo[128][GST];
    __shared__ unsigned Bhi[128][GST], Blo[128][GST];

    const int tid  = threadIdx.x;
    const int lane = tid & 31;
    const int warp = tid >> 5;
    const int wm   = warp >> 2;     // 0..1
    const int wn   = warp & 3;      // 0..3
    const int m0   = blockIdx.x * 128;
    const int n0   = blockIdx.y * 128;
    const int lr   = lane >> 2;     // 0..7
    const int lc   = lane & 3;      // 0..3

    float acc[4][4][4];
#pragma unroll
    for (int i = 0; i < 4; i++)
#pragma unroll
        for (int j = 0; j < 4; j++)
#pragma unroll
            for (int r = 0; r < 4; r++) acc[i][j][r] = 0.f;

    float4 pa[4], pb[4];
    const float4 fz = make_float4(0.f, 0.f, 0.f, 0.f);

    // preload first k-tile (k0 = 0)
#pragma unroll
    for (int it = 0; it < 4; it++) {
        const int idx = tid + it * 256;       // 0..1023
        const int row = idx >> 3;             // 0..127
        const int c4  = (idx & 7) << 2;       // 0..28
        pa[it] = *(const float4*)&A[(long)(m0 + row) * HIDDEN + c4];
        pb[it] = (n0 + row < HIDDEN) ? *(const float4*)&Bw[(long)(n0 + row) * HIDDEN + c4] : fz;
    }

    for (int kt = 0; kt < 38; kt++) {
        const int k0 = kt * 32;
        // split + store current tile
#pragma unroll
        for (int it = 0; it < 4; it++) {
            const int idx = tid + it * 256;
            const int row = idx >> 3;
            const int u   = (idx & 7) << 1;   // u32 col 0..14
            unsigned h0, l0, h1, l1;
            split2(pa[it].x, pa[it].y, h0, l0);
            split2(pa[it].z, pa[it].w, h1, l1);
            *(uint2*)&Ahi[row][u] = make_uint2(h0, h1);
            *(uint2*)&Alo[row][u] = make_uint2(l0, l1);
            split2(pb[it].x, pb[it].y, h0, l0);
            split2(pb[it].z, pb[it].w, h1, l1);
            *(uint2*)&Bhi[row][u] = make_uint2(h0, h1);
            *(uint2*)&Blo[row][u] = make_uint2(l0, l1);
        }
        __syncthreads();

        // prefetch next tile
        if (kt + 1 < 38) {
            const int kn = k0 + 32;
#pragma unroll
            for (int it = 0; it < 4; it++) {
                const int idx = tid + it * 256;
                const int row = idx >> 3;
                const int c4  = (idx & 7) << 2;
                const bool ok = (kn + c4 < HIDDEN);
                pa[it] = ok ? *(const float4*)&A[(long)(m0 + row) * HIDDEN + kn + c4] : fz;
                pb[it] = (ok && n0 + row < HIDDEN)
                         ? *(const float4*)&Bw[(long)(n0 + row) * HIDDEN + kn + c4] : fz;
            }
        }

#pragma unroll
        for (int s = 0; s < 2; s++) {
            unsigned bh_[4][2], bl_[4][2];
#pragma unroll
            for (int nt = 0; nt < 4; nt++) {
                const int n = wn * 32 + nt * 8 + lr;
                bh_[nt][0] = Bhi[n][8 * s + lc];
                bh_[nt][1] = Bhi[n][8 * s + 4 + lc];
                bl_[nt][0] = Blo[n][8 * s + lc];
                bl_[nt][1] = Blo[n][8 * s + 4 + lc];
            }
#pragma unroll
            for (int mt = 0; mt < 4; mt++) {
                const int m = wm * 64 + mt * 16 + lr;
                unsigned ah[4], al[4];
                ah[0] = Ahi[m][8 * s + lc];     ah[1] = Ahi[m + 8][8 * s + lc];
                ah[2] = Ahi[m][8 * s + 4 + lc]; ah[3] = Ahi[m + 8][8 * s + 4 + lc];
                al[0] = Alo[m][8 * s + lc];     al[1] = Alo[m + 8][8 * s + lc];
                al[2] = Alo[m][8 * s + 4 + lc]; al[3] = Alo[m + 8][8 * s + 4 + lc];
#pragma unroll
                for (int nt = 0; nt < 4; nt++) {
                    mma16(acc[mt][nt], ah, bh_[nt]);
                    mma16(acc[mt][nt], ah, bl_[nt]);
                    mma16(acc[mt][nt], al, bh_[nt]);
                }
            }
        }
        __syncthreads();
    }

    // Epilogue
#pragma unroll
    for (int mt = 0; mt < 4; mt++) {
#pragma unroll
        for (int nt = 0; nt < 4; nt++) {
            const int m = m0 + wm * 64 + mt * 16 + lr;
            const int n = n0 + wn * 32 + nt * 8 + lc * 2;
#pragma unroll
            for (int half = 0; half < 2; half++) {
                const int mm = m + half * 8;
                const int b_ = mm >> 11;
                const int s_ = mm & (S_LEN - 1);
#pragma unroll
                for (int cj = 0; cj < 2; cj++) {
                    const int nn = n + cj;
                    if (nn < HIDDEN) {
                        const float v = acc[mt][nt][half * 2 + cj];
                        if (scatter == 1) {
                            const int h = nn / DHEAD, d = nn % DHEAD;
                            C[(((long)b_ * NHEAD + h) * S_LEN + s_) * DHEAD + d] = v;
                        } else if (scatter == 2) {
                            const int h = nn / DHEAD, d = nn % DHEAD;
                            C[(((long)b_ * NHEAD + h) * DHEAD + d) * S_LEN + s_] = v;
                        } else {
                            C[(long)mm * HIDDEN + nn] = v;
                        }
                    }
                }
            }
        }
    }
}

// ---------------------------------------------------------------------------
// Flash attention, bf16 3-mma. 256 threads (8 warps), q-tile 128, kv 64.
// Q pre-split once (packed bf16x2, stride 52 u32). K split per tile (stride 52).
// V^T (from gmem (b,h,d,s)) split per tile, stride 36. P stays in registers.
// d padded to 104: 6 x k16 steps + 1 x k8 step.
// ---------------------------------------------------------------------------
#define QST 52
#define VTS 36
#define QHI_OFF  0                      // 128*52 = 6656
#define QLO_OFF  6656
#define KHI_OFF  13312                  // 64*52 = 3328
#define KLO_OFF  16640
#define VTHI_OFF 19968                  // 104*36 = 3744
#define VTLO_OFF 23712
#define BIAS_OFF 27456                  // 64
#define FL_SMEM_U32 27520
#define FL_SMEM_BYTES (FL_SMEM_U32 * 4)
#define NDT 13

__global__ __launch_bounds__(256, 2) void flash_kernel(
    const float* __restrict__ alibi, const float* __restrict__ mask,
    const int* __restrict__ layer_index,
    const float* __restrict__ Q, const float* __restrict__ K,
    const float* __restrict__ V, float* __restrict__ O)
{
    extern __shared__ unsigned smu[];
    unsigned* Qhi  = smu + QHI_OFF;
    unsigned* Qlo  = smu + QLO_OFF;
    unsigned* Khi  = smu + KHI_OFF;
    unsigned* Klo  = smu + KLO_OFF;
    unsigned* Vthi = smu + VTHI_OFF;
    unsigned* Vtlo = smu + VTLO_OFF;
    float*    bias = (float*)(smu + BIAS_OFF);

    const int tid  = threadIdx.x;
    const int lane = tid & 31;
    const int w    = tid >> 5;          // 0..7
    const int lr   = lane >> 2;         // 0..7
    const int lc   = lane & 3;          // 0..3
    const int bh   = blockIdx.x;        // 0..47
    const int q0   = blockIdx.y * 128;
    const int b_   = bh / NHEAD;

    const float inv = 1.f / (float)(layer_index[0] + 1);
    const float sc  = 10.f * inv;       // sqrt(100)/(L+1)

    // zero pads: Q/K u32 cols 50,51 (d = 100..103); Vt rows 100..103
    if (tid < 128) {
        Qhi[tid * QST + 50] = 0u; Qhi[tid * QST + 51] = 0u;
        Qlo[tid * QST + 50] = 0u; Qlo[tid * QST + 51] = 0u;
        if (tid < 64) {
            Khi[tid * QST + 50] = 0u; Khi[tid * QST + 51] = 0u;
            Klo[tid * QST + 50] = 0u; Klo[tid * QST + 51] = 0u;
        }
    }
    for (int id = tid; id < 4 * VTS; id += 256) {
        Vthi[(100 + id / VTS) * VTS + (id % VTS)] = 0u;
        Vtlo[(100 + id / VTS) * VTS + (id % VTS)] = 0u;
    }

    // Load + split Q tile once (128 rows x 100)
    for (int id = tid; id < 128 * 25; id += 256) {
        const int r  = id / 25;
        const int c4 = (id % 25) * 4;
        float4 v = *(const float4*)&Q[((long)bh * S_LEN + q0 + r) * DHEAD + c4];
        unsigned h0, l0, h1, l1;
        split2(v.x, v.y, h0, l0);
        split2(v.z, v.w, h1, l1);
        *(uint2*)&Qhi[r * QST + (c4 >> 1)] = make_uint2(h0, h1);
        *(uint2*)&Qlo[r * QST + (c4 >> 1)] = make_uint2(l0, l1);
    }

    float oacc[NDT][4];
#pragma unroll
    for (int nt = 0; nt < NDT; nt++)
#pragma unroll
        for (int r = 0; r < 4; r++) oacc[nt][r] = 0.f;
    float mrow0 = -1e30f, mrow1 = -1e30f, lsum0 = 0.f, lsum1 = 0.f;

    const int ar = 16 * w + lr;   // this thread's first q-row (local)

    for (int kt = 0; kt < S_LEN / 64; kt++) {
        const int k0g = kt * 64;
        __syncthreads();   // prior-iteration readers done before overwrite

        // K tile: rows = key, cols = d (packed pairs)
        for (int id = tid; id < 64 * 25; id += 256) {
            const int r  = id / 25;
            const int c4 = (id % 25) * 4;
            float4 v = *(const float4*)&K[((long)bh * S_LEN + k0g + r) * DHEAD + c4];
            unsigned h0, l0, h1, l1;
            split2(v.x, v.y, h0, l0);
            split2(v.z, v.w, h1, l1);
            *(uint2*)&Khi[r * QST + (c4 >> 1)] = make_uint2(h0, h1);
            *(uint2*)&Klo[r * QST + (c4 >> 1)] = make_uint2(l0, l1);
        }
        // V^T tile: rows = d (0..99), cols = key (packed pairs). V is (b,h,d,s).
        for (int id = tid; id < 100 * 16; id += 256) {
            const int d  = id / 16;
            const int c4 = (id % 16) * 4;
            float4 v = *(const float4*)&V[((long)bh * DHEAD + d) * S_LEN + k0g + c4];
            unsigned h0, l0, h1, l1;
            split2(v.x, v.y, h0, l0);
            split2(v.z, v.w, h1, l1);
            *(uint2*)&Vthi[d * VTS + (c4 >> 1)] = make_uint2(h0, h1);
            *(uint2*)&Vtlo[d * VTS + (c4 >> 1)] = make_uint2(l0, l1);
        }
        if (tid < 64) {
            const int t = k0g + tid;
            bias[tid] = alibi[(long)bh * S_LEN + t] * inv + mask[(long)b_ * S_LEN + t];
        }
        __syncthreads();

        // ---- S = Q K^T ----
        float sacc[8][4];
#pragma unroll
        for (int nt = 0; nt < 8; nt++)
#pragma unroll
            for (int r = 0; r < 4; r++) sacc[nt][r] = 0.f;

#pragma unroll
        for (int s = 0; s < 6; s++) {
            unsigned ah[4], al[4];
            ah[0] = Qhi[ar * QST + 8 * s + lc];           ah[1] = Qhi[(ar + 8) * QST + 8 * s + lc];
            ah[2] = Qhi[ar * QST + 8 * s + 4 + lc];       ah[3] = Qhi[(ar + 8) * QST + 8 * s + 4 + lc];
            al[0] = Qlo[ar * QST + 8 * s + lc];           al[1] = Qlo[(ar + 8) * QST + 8 * s + lc];
            al[2] = Qlo[ar * QST + 8 * s + 4 + lc];       al[3] = Qlo[(ar + 8) * QST + 8 * s + 4 + lc];
#pragma unroll
            for (int nt = 0; nt < 8; nt++) {
                const int bn = nt * 8 + lr;
                unsigned bh2[2], bl2[2];
                bh2[0] = Khi[bn * QST + 8 * s + lc];
                bh2[1] = Khi[bn * QST + 8 * s + 4 + lc];
                bl2[0] = Klo[bn * QST + 8 * s + lc];
                bl2[1] = Klo[bn * QST + 8 * s + 4 + lc];
                mma16(sacc[nt], ah, bh2);
                mma16(sacc[nt], ah, bl2);
                mma16(sacc[nt], al, bh2);
            }
        }
        {   // k8 tail (d 96..103; 100..103 are zero pad)
            unsigned ah2[2], al2[2];
            ah2[0] = Qhi[ar * QST + 48 + lc]; ah2[1] = Qhi[(ar + 8) * QST + 48 + lc];
            al2[0] = Qlo[ar * QST + 48 + lc]; al2[1] = Qlo[(ar + 8) * QST + 48 + lc];
#pragma unroll
            for (int nt = 0; nt < 8; nt++) {
                const int bn = nt * 8 + lr;
                const unsigned bhv = Khi[bn * QST + 48 + lc];
                const unsigned blv = Klo[bn * QST + 48 + lc];
                mma8b(sacc[nt], ah2, bhv);
                mma8b(sacc[nt], ah2, blv);
                mma8b(sacc[nt], al2, bhv);
            }
        }

        // ---- scale + bias ----
#pragma unroll
        for (int nt = 0; nt < 8; nt++) {
            const int col = nt * 8 + lc * 2;
            const float b0v = bias[col], b1v = bias[col + 1];
            sacc[nt][0] = sacc[nt][0] * sc + b0v;
            sacc[nt][1] = sacc[nt][1] * sc + b1v;
            sacc[nt][2] = sacc[nt][2] * sc + b0v;
            sacc[nt][3] = sacc[nt][3] * sc + b1v;
        }

        // ---- online softmax ----
        float rm0 = -1e30f, rm1 = -1e30f;
#pragma unroll
        for (int nt = 0; nt < 8; nt++) {
            rm0 = fmaxf(rm0, fmaxf(sacc[nt][0], sacc[nt][1]));
            rm1 = fmaxf(rm1, fmaxf(sacc[nt][2], sacc[nt][3]));
        }
        rm0 = fmaxf(rm0, __shfl_xor_sync(0xffffffffu, rm0, 1));
        rm0 = fmaxf(rm0, __shfl_xor_sync(0xffffffffu, rm0, 2));
        rm1 = fmaxf(rm1, __shfl_xor_sync(0xffffffffu, rm1, 1));
        rm1 = fmaxf(rm1, __shfl_xor_sync(0xffffffffu, rm1, 2));
        const float mn0 = fmaxf(mrow0, rm0);
        const float mn1 = fmaxf(mrow1, rm1);
        const float f0  = __expf(mrow0 - mn0);
        const float f1  = __expf(mrow1 - mn1);
        float rs0 = 0.f, rs1 = 0.f;
#pragma unroll
        for (int nt = 0; nt < 8; nt++) {
            sacc[nt][0] = __expf(sacc[nt][0] - mn0);
            sacc[nt][1] = __expf(sacc[nt][1] - mn0);
            sacc[nt][2] = __expf(sacc[nt][2] - mn1);
            sacc[nt][3] = __expf(sacc[nt][3] - mn1);
            rs0 += sacc[nt][0] + sacc[nt][1];
            rs1 += sacc[nt][2] + sacc[nt][3];
        }
        rs0 += __shfl_xor_sync(0xffffffffu, rs0, 1);
        rs0 += __shfl_xor_sync(0xffffffffu, rs0, 2);
        rs1 += __shfl_xor_sync(0xffffffffu, rs1, 1);
        rs1 += __shfl_xor_sync(0xffffffffu, rs1, 2);
        lsum0 = lsum0 * f0 + rs0;
        lsum1 = lsum1 * f1 + rs1;
        mrow0 = mn0;
        mrow1 = mn1;
#pragma unroll
        for (int nt = 0; nt < NDT; nt++) {
            oacc[nt][0] *= f0; oacc[nt][1] *= f0;
            oacc[nt][2] *= f1; oacc[nt][3] *= f1;
        }

        // ---- pack P into bf16 A-fragments (registers only) ----
        unsigned aH[8][2], aL[8][2];
#pragma unroll
        for (int nt = 0; nt < 8; nt++) {
            split2(sacc[nt][0], sacc[nt][1], aH[nt][0], aL[nt][0]);
            split2(sacc[nt][2], sacc[nt][3], aH[nt][1], aL[nt][1]);
        }

        // ---- O += P V (k = key, 4 x k16) ----
#pragma unroll
        for (int ks = 0; ks < 4; ks++) {
            unsigned pah[4], pal[4];
            pah[0] = aH[2 * ks][0];     pah[1] = aH[2 * ks][1];
            pah[2] = aH[2 * ks + 1][0]; pah[3] = aH[2 * ks + 1][1];
            pal[0] = aL[2 * ks][0];     pal[1] = aL[2 * ks][1];
            pal[2] = aL[2 * ks + 1][0]; pal[3] = aL[2 * ks + 1][1];
#pragma unroll
            for (int nt = 0; nt < NDT; nt++) {
                const int bn = nt * 8 + lr;     // d index
                unsigned bh2[2], bl2[2];
                bh2[0] = Vthi[bn * VTS + 8 * ks + lc];
                bh2[1] = Vthi[bn * VTS + 8 * ks + 4 + lc];
                bl2[0] = Vtlo[bn * VTS + 8 * ks + lc];
                bl2[1] = Vtlo[bn * VTS + 8 * ks + 4 + lc];
                mma16(oacc[nt], pah, bh2);
                mma16(oacc[nt], pah, bl2);
                mma16(oacc[nt], pal, bh2);
            }
        }
    }

    // ---- normalize + store (b,h,s,d) ----
    const float il0 = 1.f / lsum0;
    const float il1 = 1.f / lsum1;
    const int r0 = q0 + ar;
    const long base0 = ((long)bh * S_LEN + r0) * DHEAD;
    const long base1 = ((long)bh * S_LEN + r0 + 8) * DHEAD;
#pragma unroll
    for (int nt = 0; nt < NDT; nt++) {
        const int col = nt * 8 + lc * 2;
        if (col < DHEAD) {
            O[base0 + col] = oacc[nt][0] * il0;
            O[base1 + col] = oacc[nt][2] * il1;
        }
        if (col + 1 < DHEAD) {
            O[base0 + col + 1] = oacc[nt][1] * il0;
            O[base1 + col + 1] = oacc[nt][3] * il1;
        }
    }
}

// ---------------------------------------------------------------------------
// Launch
// ---------------------------------------------------------------------------
extern "C" void kernel_launch(void* const* d_in, const int* in_sizes, int n_in,
                              void* d_out, int out_size)
{
    const float* x     = (const float*)d_in[0];
    const float* alibi = (const float*)d_in[1];
    const float* mask  = (const float*)d_in[2];
    const float* wq    = (const float*)d_in[3];
    const float* wk    = (const float*)d_in[4];
    const float* wv    = (const float*)d_in[5];
    const float* wo    = (const float*)d_in[6];
    const int*   li    = (const int*)d_in[7];
    float* out = (float*)d_out;

    float *Qp, *Kp, *Vp, *Op;
    cudaGetSymbolAddress((void**)&Qp, g_Q);
    cudaGetSymbolAddress((void**)&Kp, g_K);
    cudaGetSymbolAddress((void**)&Vp, g_V);
    cudaGetSymbolAddress((void**)&Op, g_O);

    cudaFuncSetAttribute(flash_kernel,
                         cudaFuncAttributeMaxDynamicSharedMemorySize, FL_SMEM_BYTES);

    dim3 gg(M_TOT / 128, (HIDDEN + 127) / 128);   // (64, 10)
    gemm_bf16_kernel<<<gg, 256>>>(x, wq, Qp, 1);
    gemm_bf16_kernel<<<gg, 256>>>(x, wk, Kp, 1);
    gemm_bf16_kernel<<<gg, 256>>>(x, wv, Vp, 2);   // V transposed (b,h,d,s)

    flash_kernel<<<dim3(BH, S_LEN / 128), 256, FL_SMEM_BYTES>>>(
        alibi, mask, li, Qp, Kp, Vp, Op);

    gemm_bf16_kernel<<<gg, 256>>>(Op, wo, out, 0);
}

// round 7
// speedup vs baseline: 3.4582x; 1.3397x over previous
#include <cuda_runtime.h>
#include <cuda_bf16.h>
#include <cstdint>
#include <math.h>

// Problem constants
#define BATCH  4
#define S_LEN  2048
#define NHEAD  12
#define DHEAD  100
#define HIDDEN 1200
#define M_TOT  (BATCH * S_LEN)          // 8192
#define BH     (BATCH * NHEAD)          // 48
#define PCOLS  1216                     // K padded (19*64)
#define PU32   608                      // PCOLS/2 in u32
#define PROWSW 1280                     // weight rows padded

// ---------------------------------------------------------------------------
// Scratch (all interchange data is pre-split bf16 hi/lo)
// ---------------------------------------------------------------------------
__device__ __align__(16) __nv_bfloat16 g_xhi[M_TOT * PCOLS];
__device__ __align__(16) __nv_bfloat16 g_xlo[M_TOT * PCOLS];
__device__ __align__(16) __nv_bfloat16 g_whi[4][PROWSW * PCOLS];
__device__ __align__(16) __nv_bfloat16 g_wlo[4][PROWSW * PCOLS];
// Q,K: (bh, s, 52 u32) packed bf16 pairs along d (pads 50,51 zero)
__device__ __align__(16) unsigned g_qhi[BH * S_LEN * 52];
__device__ __align__(16) unsigned g_qlo[BH * S_LEN * 52];
__device__ __align__(16) unsigned g_khi[BH * S_LEN * 52];
__device__ __align__(16) unsigned g_klo[BH * S_LEN * 52];
// V^T: (bh, 104 d-rows, 1024 u32) packed pairs along s (d rows 100..103 zero)
__device__ __align__(16) unsigned g_vthi[BH * 104 * 1024];
__device__ __align__(16) unsigned g_vtlo[BH * 104 * 1024];
// O: padded (8192, 608 u32) packed pairs (cols 600..607 zero)
__device__ __align__(16) unsigned g_ohi[M_TOT * PU32];
__device__ __align__(16) unsigned g_olo[M_TOT * PU32];

// ---------------------------------------------------------------------------
// BF16 helpers + mma.sync
// ---------------------------------------------------------------------------
__device__ __forceinline__ unsigned cvt2(float even, float odd) {
    unsigned r;
    asm("cvt.rn.bf16x2.f32 %0, %1, %2;" : "=r"(r) : "f"(odd), "f"(even));
    return r;
}
__device__ __forceinline__ float bf_lo(unsigned p) { return __uint_as_float(p << 16); }
__device__ __forceinline__ float bf_hi(unsigned p) { return __uint_as_float(p & 0xFFFF0000u); }
__device__ __forceinline__ void split2(float e, float o, unsigned& h, unsigned& l) {
    h = cvt2(e, o);
    l = cvt2(e - bf_lo(h), o - bf_hi(h));
}
__device__ __forceinline__ void mma16(float* c, const unsigned* a, const unsigned* b) {
    asm volatile(
        "mma.sync.aligned.m16n8k16.row.col.f32.bf16.bf16.f32 "
        "{%0,%1,%2,%3}, {%4,%5,%6,%7}, {%8,%9}, {%0,%1,%2,%3};\n"
        : "+f"(c[0]), "+f"(c[1]), "+f"(c[2]), "+f"(c[3])
        : "r"(a[0]), "r"(a[1]), "r"(a[2]), "r"(a[3]), "r"(b[0]), "r"(b[1]));
}
__device__ __forceinline__ void mma8b(float* c, const unsigned* a, unsigned b) {
    asm volatile(
        "mma.sync.aligned.m16n8k8.row.col.f32.bf16.bf16.f32 "
        "{%0,%1,%2,%3}, {%4,%5}, {%6}, {%0,%1,%2,%3};\n"
        : "+f"(c[0]), "+f"(c[1]), "+f"(c[2]), "+f"(c[3])
        : "r"(a[0]), "r"(a[1]), "r"(b));
}

// ---------------------------------------------------------------------------
// Prep: fp32 -> bf16 hi/lo with zero padding
// ---------------------------------------------------------------------------
__global__ void split_pad_kernel(const float* __restrict__ src,
                                 __nv_bfloat16* __restrict__ hi,
                                 __nv_bfloat16* __restrict__ lo,
                                 int rows, int cols, int pcols, int total)
{
    const int i = blockIdx.x * 256 + threadIdx.x;
    if (i >= total) return;
    const int r = i / pcols;
    const int c = i - r * pcols;
    float v = (r < rows && c < cols) ? src[(long)r * cols + c] : 0.f;
    __nv_bfloat16 h = __float2bfloat16(v);
    hi[i] = h;
    lo[i] = __float2bfloat16(v - __bfloat162float(h));
}

// Zero pad regions: Q/K u32 cols 50,51; Vt d-rows 100..103; O u32 cols 600..607
__global__ void init_pads_kernel(unsigned* qhi, unsigned* qlo, unsigned* khi, unsigned* klo,
                                 unsigned* vthi, unsigned* vtlo, unsigned* ohi, unsigned* olo)
{
    const int i = blockIdx.x * 256 + threadIdx.x;
    if (i < BH * S_LEN * 2) {
        const int r = i >> 1;
        const long a = (long)r * 52 + 50 + (i & 1);
        qhi[a] = 0u; qlo[a] = 0u; khi[a] = 0u; klo[a] = 0u;
    }
    if (i < BH * 4 * 1024) {
        const int bh = i >> 12;
        const long a = ((long)bh * 104 + 100) * 1024 + (i & 4095);
        vthi[a] = 0u; vtlo[a] = 0u;
    }
    if (i < M_TOT * 8) {
        const long a = (long)(i >> 3) * PU32 + 600 + (i & 7);
        ohi[a] = 0u; olo[a] = 0u;
    }
}

// ---------------------------------------------------------------------------
// GEMM (bf16 3-mma split, pre-split operands): C[m,n] = sum_k A[m,k]*W[n,k]
// 128x128 tile, BK=64 bf16 (32 u32 per row), 256 threads, warp tile 64x32.
// smem u32 arrays [128][36] (stride 36 conflict-free): AHI ALO BHI BLO.
// Inner loop: 4 k16-steps per chunk (8 u32 each).  <-- was 8 in R6: OOB bug
// mode 0: f32 row-major (M,1200);  mode 1: Q/K hi-lo layout;  mode 3: V^T.
// ---------------------------------------------------------------------------
#define GS_AHI 0
#define GS_ALO 18432
#define GS_BHI 36864
#define GS_BLO 55296
#define GT_SMEM 73728

__global__ __launch_bounds__(256, 2) void gemm_ps_kernel(
    const __nv_bfloat16* __restrict__ Ahi_g, const __nv_bfloat16* __restrict__ Alo_g,
    const __nv_bfloat16* __restrict__ Bhi_g, const __nv_bfloat16* __restrict__ Blo_g,
    float* __restrict__ Cf, unsigned* __restrict__ Chi, unsigned* __restrict__ Clo,
    int mode)
{
    extern __shared__ unsigned char smb[];
    unsigned* AHI = (unsigned*)(smb + GS_AHI);
    unsigned* ALO = (unsigned*)(smb + GS_ALO);
    unsigned* BHI = (unsigned*)(smb + GS_BHI);
    unsigned* BLO = (unsigned*)(smb + GS_BLO);

    const int tid  = threadIdx.x;
    const int lane = tid & 31;
    const int warp = tid >> 5;
    const int wm   = warp >> 2;     // 0..1
    const int wn   = warp & 3;      // 0..3
    const int m0   = blockIdx.x * 128;
    const int n0   = blockIdx.y * 128;
    const int lr   = lane >> 2;
    const int lc   = lane & 3;

    const unsigned* Ahi_u = (const unsigned*)Ahi_g;
    const unsigned* Alo_u = (const unsigned*)Alo_g;
    const unsigned* Bhi_u = (const unsigned*)Bhi_g;
    const unsigned* Blo_u = (const unsigned*)Blo_g;

    float acc[4][4][4];
#pragma unroll
    for (int i = 0; i < 4; i++)
#pragma unroll
        for (int j = 0; j < 4; j++)
#pragma unroll
            for (int r = 0; r < 4; r++) acc[i][j][r] = 0.f;

    const int lrow = tid >> 3;        // 0..31
    const int cn   = tid & 7;         // 16B chunk

    for (int ch = 0; ch < PCOLS / 64; ch++) {
        __syncthreads();
#pragma unroll
        for (int q = 0; q < 4; q++) {
            const int row = lrow + q * 32;
            const long a_off = (long)(m0 + row) * PU32 + ch * 32 + cn * 4;
            const long b_off = (long)(n0 + row) * PU32 + ch * 32 + cn * 4;
            const int so = row * 36 + cn * 4;
            *(uint4*)&AHI[so] = *(const uint4*)&Ahi_u[a_off];
            *(uint4*)&ALO[so] = *(const uint4*)&Alo_u[a_off];
            *(uint4*)&BHI[so] = *(const uint4*)&Bhi_u[b_off];
            *(uint4*)&BLO[so] = *(const uint4*)&Blo_u[b_off];
        }
        __syncthreads();

#pragma unroll
        for (int s = 0; s < 4; s++) {          // FIXED: 4 k16-steps (32 u32 of BK)
            unsigned bhv[4][2], blv[4][2];
#pragma unroll
            for (int nt = 0; nt < 4; nt++) {
                const int n = wn * 32 + nt * 8 + lr;
                bhv[nt][0] = BHI[n * 36 + 8 * s + lc];
                bhv[nt][1] = BHI[n * 36 + 8 * s + 4 + lc];
                blv[nt][0] = BLO[n * 36 + 8 * s + lc];
                blv[nt][1] = BLO[n * 36 + 8 * s + 4 + lc];
            }
#pragma unroll
            for (int mt = 0; mt < 4; mt++) {
                const int m = wm * 64 + mt * 16 + lr;
                unsigned ah[4], al[4];
                ah[0] = AHI[m * 36 + 8 * s + lc];       ah[1] = AHI[(m + 8) * 36 + 8 * s + lc];
                ah[2] = AHI[m * 36 + 8 * s + 4 + lc];   ah[3] = AHI[(m + 8) * 36 + 8 * s + 4 + lc];
                al[0] = ALO[m * 36 + 8 * s + lc];       al[1] = ALO[(m + 8) * 36 + 8 * s + lc];
                al[2] = ALO[m * 36 + 8 * s + 4 + lc];   al[3] = ALO[(m + 8) * 36 + 8 * s + 4 + lc];
#pragma unroll
                for (int nt = 0; nt < 4; nt++) {
                    mma16(acc[mt][nt], ah, bhv[nt]);
                    mma16(acc[mt][nt], ah, blv[nt]);
                    mma16(acc[mt][nt], al, bhv[nt]);
                }
            }
        }
    }

    // ---- Epilogue ----
    if (mode == 3) {
        // stage C into smem (reuses operand smem), transpose-store as V^T pairs
        __syncthreads();
        float* Ct = (float*)smb;   // [128 n][129 m]
#pragma unroll
        for (int mt = 0; mt < 4; mt++)
#pragma unroll
            for (int nt = 0; nt < 4; nt++) {
                const int mL = wm * 64 + mt * 16 + lr;
                const int nL = wn * 32 + nt * 8 + lc * 2;
                Ct[(nL)     * 129 + mL]     = acc[mt][nt][0];
                Ct[(nL + 1) * 129 + mL]     = acc[mt][nt][1];
                Ct[(nL)     * 129 + mL + 8] = acc[mt][nt][2];
                Ct[(nL + 1) * 129 + mL + 8] = acc[mt][nt][3];
            }
        __syncthreads();
#pragma unroll
        for (int it = 0; it < 32; it++) {
            const int idx = tid + it * 256;    // 0..8191
            const int nL  = idx >> 6;          // 0..127
            const int mp  = idx & 63;          // m-pair
            const int n   = n0 + nL;
            if (n < HIDDEN) {
                const float c0 = Ct[nL * 129 + 2 * mp];
                const float c1 = Ct[nL * 129 + 2 * mp + 1];
                const int m = m0 + 2 * mp;
                const int b_ = m >> 11, s_ = m & (S_LEN - 1);
                const int h_ = n / DHEAD, d_ = n % DHEAD;
                unsigned h, l;
                split2(c0, c1, h, l);
                const long a = ((long)(b_ * NHEAD + h_) * 104 + d_) * 1024 + (s_ >> 1);
                Chi[a] = h; Clo[a] = l;
            }
        }
        return;
    }

#pragma unroll
    for (int mt = 0; mt < 4; mt++) {
#pragma unroll
        for (int nt = 0; nt < 4; nt++) {
            const int nn = n0 + wn * 32 + nt * 8 + lc * 2;
            if (nn >= HIDDEN) continue;
#pragma unroll
            for (int half = 0; half < 2; half++) {
                const int mm = m0 + wm * 64 + mt * 16 + lr + half * 8;
                const float c0 = acc[mt][nt][half * 2];
                const float c1 = acc[mt][nt][half * 2 + 1];
                if (mode == 0) {
                    *(float2*)&Cf[(long)mm * HIDDEN + nn] = make_float2(c0, c1);
                } else {
                    const int b_ = mm >> 11, s_ = mm & (S_LEN - 1);
                    const int h_ = nn / DHEAD, d_ = nn % DHEAD;
                    unsigned h, l;
                    split2(c0, c1, h, l);
                    const long a = ((long)(b_ * NHEAD + h_) * S_LEN + s_) * 52 + (d_ >> 1);
                    Chi[a] = h; Clo[a] = l;
                }
            }
        }
    }
}

// ---------------------------------------------------------------------------
// Flash attention (bf16 3-mma). 256 threads, q-tile 128, kv 64.
// All operands arrive pre-split bf16 — tile loads are pure uint4 copies.
// ---------------------------------------------------------------------------
#define QST 52
#define VTS 36
#define QHI_OFF  0
#define QLO_OFF  6656
#define KHI_OFF  13312
#define KLO_OFF  16640
#define VTHI_OFF 19968
#define VTLO_OFF 23712
#define BIAS_OFF 27456
#define FL_SMEM_U32 27520
#define FL_SMEM_BYTES (FL_SMEM_U32 * 4)
#define NDT 13

__global__ __launch_bounds__(256, 2) void flash_kernel(
    const float* __restrict__ alibi, const float* __restrict__ mask,
    const int* __restrict__ layer_index,
    const unsigned* __restrict__ qhi_g, const unsigned* __restrict__ qlo_g,
    const unsigned* __restrict__ khi_g, const unsigned* __restrict__ klo_g,
    const unsigned* __restrict__ vthi_g, const unsigned* __restrict__ vtlo_g,
    unsigned* __restrict__ ohi_g, unsigned* __restrict__ olo_g)
{
    extern __shared__ unsigned smu[];
    unsigned* Qhi  = smu + QHI_OFF;
    unsigned* Qlo  = smu + QLO_OFF;
    unsigned* Khi  = smu + KHI_OFF;
    unsigned* Klo  = smu + KLO_OFF;
    unsigned* Vthi = smu + VTHI_OFF;
    unsigned* Vtlo = smu + VTLO_OFF;
    float*    bias = (float*)(smu + BIAS_OFF);

    const int tid  = threadIdx.x;
    const int lane = tid & 31;
    const int w    = tid >> 5;
    const int lr   = lane >> 2;
    const int lc   = lane & 3;
    const int bh   = blockIdx.x;
    const int q0   = blockIdx.y * 128;
    const int b_   = bh / NHEAD;
    const int h_   = bh % NHEAD;

    const float inv = 1.f / (float)(layer_index[0] + 1);
    const float sc  = 10.f * inv;

    // Q tile: straight copy (pads included, pre-zeroed)
    {
        const long qbase = ((long)bh * S_LEN + q0) * 52;
        for (int id = tid; id < 128 * 13; id += 256) {
            const int r  = id / 13;
            const int c4 = (id % 13) * 4;
            *(uint4*)&Qhi[r * QST + c4] = *(const uint4*)&qhi_g[qbase + r * 52 + c4];
            *(uint4*)&Qlo[r * QST + c4] = *(const uint4*)&qlo_g[qbase + r * 52 + c4];
        }
    }

    float oacc[NDT][4];
#pragma unroll
    for (int nt = 0; nt < NDT; nt++)
#pragma unroll
        for (int r = 0; r < 4; r++) oacc[nt][r] = 0.f;
    float mrow0 = -1e30f, mrow1 = -1e30f, lsum0 = 0.f, lsum1 = 0.f;

    const int ar = 16 * w + lr;

    for (int kt = 0; kt < S_LEN / 64; kt++) {
        const int k0g = kt * 64;
        __syncthreads();

        {
            const long kbase = ((long)bh * S_LEN + k0g) * 52;
            for (int id = tid; id < 64 * 13; id += 256) {
                const int r  = id / 13;
                const int c4 = (id % 13) * 4;
                *(uint4*)&Khi[r * QST + c4] = *(const uint4*)&khi_g[kbase + r * 52 + c4];
                *(uint4*)&Klo[r * QST + c4] = *(const uint4*)&klo_g[kbase + r * 52 + c4];
            }
            const long vbase = (long)bh * 104 * 1024 + (k0g >> 1);
            for (int id = tid; id < 104 * 8; id += 256) {
                const int d  = id / 8;
                const int c4 = (id % 8) * 4;
                *(uint4*)&Vthi[d * VTS + c4] = *(const uint4*)&vthi_g[vbase + d * 1024 + c4];
                *(uint4*)&Vtlo[d * VTS + c4] = *(const uint4*)&vtlo_g[vbase + d * 1024 + c4];
            }
        }
        if (tid < 64) {
            const int t = k0g + tid;
            bias[tid] = alibi[(long)bh * S_LEN + t] * inv + mask[(long)b_ * S_LEN + t];
        }
        __syncthreads();

        // ---- S = Q K^T ----
        float sacc[8][4];
#pragma unroll
        for (int nt = 0; nt < 8; nt++)
#pragma unroll
            for (int r = 0; r < 4; r++) sacc[nt][r] = 0.f;

#pragma unroll
        for (int s = 0; s < 6; s++) {
            unsigned ah[4], al[4];
            ah[0] = Qhi[ar * QST + 8 * s + lc];     ah[1] = Qhi[(ar + 8) * QST + 8 * s + lc];
            ah[2] = Qhi[ar * QST + 8 * s + 4 + lc]; ah[3] = Qhi[(ar + 8) * QST + 8 * s + 4 + lc];
            al[0] = Qlo[ar * QST + 8 * s + lc];     al[1] = Qlo[(ar + 8) * QST + 8 * s + lc];
            al[2] = Qlo[ar * QST + 8 * s + 4 + lc]; al[3] = Qlo[(ar + 8) * QST + 8 * s + 4 + lc];
#pragma unroll
            for (int nt = 0; nt < 8; nt++) {
                const int bn = nt * 8 + lr;
                unsigned bh2[2], bl2[2];
                bh2[0] = Khi[bn * QST + 8 * s + lc];
                bh2[1] = Khi[bn * QST + 8 * s + 4 + lc];
                bl2[0] = Klo[bn * QST + 8 * s + lc];
                bl2[1] = Klo[bn * QST + 8 * s + 4 + lc];
                mma16(sacc[nt], ah, bh2);
                mma16(sacc[nt], ah, bl2);
                mma16(sacc[nt], al, bh2);
            }
        }
        {
            unsigned ah2[2], al2[2];
            ah2[0] = Qhi[ar * QST + 48 + lc]; ah2[1] = Qhi[(ar + 8) * QST + 48 + lc];
            al2[0] = Qlo[ar * QST + 48 + lc]; al2[1] = Qlo[(ar + 8) * QST + 48 + lc];
#pragma unroll
            for (int nt = 0; nt < 8; nt++) {
                const int bn = nt * 8 + lr;
                const unsigned bhv = Khi[bn * QST + 48 + lc];
                const unsigned blv = Klo[bn * QST + 48 + lc];
                mma8b(sacc[nt], ah2, bhv);
                mma8b(sacc[nt], ah2, blv);
                mma8b(sacc[nt], al2, bhv);
            }
        }

#pragma unroll
        for (int nt = 0; nt < 8; nt++) {
            const int col = nt * 8 + lc * 2;
            const float b0v = bias[col], b1v = bias[col + 1];
            sacc[nt][0] = sacc[nt][0] * sc + b0v;
            sacc[nt][1] = sacc[nt][1] * sc + b1v;
            sacc[nt][2] = sacc[nt][2] * sc + b0v;
            sacc[nt][3] = sacc[nt][3] * sc + b1v;
        }

        // ---- online softmax ----
        float rm0 = -1e30f, rm1 = -1e30f;
#pragma unroll
        for (int nt = 0; nt < 8; nt++) {
            rm0 = fmaxf(rm0, fmaxf(sacc[nt][0], sacc[nt][1]));
            rm1 = fmaxf(rm1, fmaxf(sacc[nt][2], sacc[nt][3]));
        }
        rm0 = fmaxf(rm0, __shfl_xor_sync(0xffffffffu, rm0, 1));
        rm0 = fmaxf(rm0, __shfl_xor_sync(0xffffffffu, rm0, 2));
        rm1 = fmaxf(rm1, __shfl_xor_sync(0xffffffffu, rm1, 1));
        rm1 = fmaxf(rm1, __shfl_xor_sync(0xffffffffu, rm1, 2));
        const float mn0 = fmaxf(mrow0, rm0);
        const float mn1 = fmaxf(mrow1, rm1);
        const float f0  = __expf(mrow0 - mn0);
        const float f1  = __expf(mrow1 - mn1);
        float rs0 = 0.f, rs1 = 0.f;
#pragma unroll
        for (int nt = 0; nt < 8; nt++) {
            sacc[nt][0] = __expf(sacc[nt][0] - mn0);
            sacc[nt][1] = __expf(sacc[nt][1] - mn0);
            sacc[nt][2] = __expf(sacc[nt][2] - mn1);
            sacc[nt][3] = __expf(sacc[nt][3] - mn1);
            rs0 += sacc[nt][0] + sacc[nt][1];
            rs1 += sacc[nt][2] + sacc[nt][3];
        }
        rs0 += __shfl_xor_sync(0xffffffffu, rs0, 1);
        rs0 += __shfl_xor_sync(0xffffffffu, rs0, 2);
        rs1 += __shfl_xor_sync(0xffffffffu, rs1, 1);
        rs1 += __shfl_xor_sync(0xffffffffu, rs1, 2);
        lsum0 = lsum0 * f0 + rs0;
        lsum1 = lsum1 * f1 + rs1;
        mrow0 = mn0;
        mrow1 = mn1;
#pragma unroll
        for (int nt = 0; nt < NDT; nt++) {
            oacc[nt][0] *= f0; oacc[nt][1] *= f0;
            oacc[nt][2] *= f1; oacc[nt][3] *= f1;
        }

        // ---- pack P to bf16 fragments (registers only) ----
        unsigned aH[8][2], aL[8][2];
#pragma unroll
        for (int nt = 0; nt < 8; nt++) {
            split2(sacc[nt][0], sacc[nt][1], aH[nt][0], aL[nt][0]);
            split2(sacc[nt][2], sacc[nt][3], aH[nt][1], aL[nt][1]);
        }

        // ---- O += P V ----
#pragma unroll
        for (int ks = 0; ks < 4; ks++) {
            unsigned pah[4], pal[4];
            pah[0] = aH[2 * ks][0];     pah[1] = aH[2 * ks][1];
            pah[2] = aH[2 * ks + 1][0]; pah[3] = aH[2 * ks + 1][1];
            pal[0] = aL[2 * ks][0];     pal[1] = aL[2 * ks][1];
            pal[2] = aL[2 * ks + 1][0]; pal[3] = aL[2 * ks + 1][1];
#pragma unroll
            for (int nt = 0; nt < NDT; nt++) {
                const int bn = nt * 8 + lr;
                unsigned bh2[2], bl2[2];
                bh2[0] = Vthi[bn * VTS + 8 * ks + lc];
                bh2[1] = Vthi[bn * VTS + 8 * ks + 4 + lc];
                bl2[0] = Vtlo[bn * VTS + 8 * ks + lc];
                bl2[1] = Vtlo[bn * VTS + 8 * ks + 4 + lc];
                mma16(oacc[nt], pah, bh2);
                mma16(oacc[nt], pah, bl2);
                mma16(oacc[nt], pal, bh2);
            }
        }
    }

    // ---- normalize + split-store O into padded (8192, 608 u32) layout ----
    const float il0 = 1.f / lsum0;
    const float il1 = 1.f / lsum1;
    const int r0 = q0 + ar;
#pragma unroll
    for (int nt = 0; nt < NDT; nt++) {
        const int col = nt * 8 + lc * 2;
        if (col < 99) {
            unsigned h, l;
            long F = (long)h_ * (S_LEN * DHEAD) + (long)r0 * DHEAD + col;
            long R = (long)b_ * S_LEN + F / HIDDEN;
            int cu = (int)(F % HIDDEN) >> 1;
            split2(oacc[nt][0] * il0, oacc[nt][1] * il0, h, l);
            ohi_g[R * PU32 + cu] = h; olo_g[R * PU32 + cu] = l;
            F += 8 * DHEAD;
            R = (long)b_ * S_LEN + F / HIDDEN;
            cu = (int)(F % HIDDEN) >> 1;
            split2(oacc[nt][2] * il1, oacc[nt][3] * il1, h, l);
            ohi_g[R * PU32 + cu] = h; olo_g[R * PU32 + cu] = l;
        }
    }
}

// ---------------------------------------------------------------------------
// Launch
// ---------------------------------------------------------------------------
extern "C" void kernel_launch(void* const* d_in, const int* in_sizes, int n_in,
                              void* d_out, int out_size)
{
    const float* x     = (const float*)d_in[0];
    const float* alibi = (const float*)d_in[1];
    const float* mask  = (const float*)d_in[2];
    const float* wts[4] = { (const float*)d_in[3], (const float*)d_in[4],
                            (const float*)d_in[5], (const float*)d_in[6] };
    const int*   li    = (const int*)d_in[7];
    float* out = (float*)d_out;

    __nv_bfloat16 *xhi, *xlo, *whi, *wlo;
    unsigned *qhi, *qlo, *khi, *klo, *vthi, *vtlo, *ohi, *olo;
    cudaGetSymbolAddress((void**)&xhi, g_xhi);
    cudaGetSymbolAddress((void**)&xlo, g_xlo);
    cudaGetSymbolAddress((void**)&whi, g_whi);
    cudaGetSymbolAddress((void**)&wlo, g_wlo);
    cudaGetSymbolAddress((void**)&qhi, g_qhi);
    cudaGetSymbolAddress((void**)&qlo, g_qlo);
    cudaGetSymbolAddress((void**)&khi, g_khi);
    cudaGetSymbolAddress((void**)&klo, g_klo);
    cudaGetSymbolAddress((void**)&vthi, g_vthi);
    cudaGetSymbolAddress((void**)&vtlo, g_vtlo);
    cudaGetSymbolAddress((void**)&ohi, g_ohi);
    cudaGetSymbolAddress((void**)&olo, g_olo);

    cudaFuncSetAttribute(flash_kernel,
                         cudaFuncAttributeMaxDynamicSharedMemorySize, FL_SMEM_BYTES);
    cudaFuncSetAttribute(gemm_ps_kernel,
                         cudaFuncAttributeMaxDynamicSharedMemorySize, GT_SMEM);

    // prep
    init_pads_kernel<<<768, 256>>>(qhi, qlo, khi, klo, vthi, vtlo, ohi, olo);
    const int totX = M_TOT * PCOLS;
    const int totW = PROWSW * PCOLS;
    split_pad_kernel<<<(totX + 255) / 256, 256>>>(x, xhi, xlo, M_TOT, HIDDEN, PCOLS, totX);
    for (int i = 0; i < 4; i++)
        split_pad_kernel<<<(totW + 255) / 256, 256>>>(
            wts[i], whi + (long)i * totW, wlo + (long)i * totW,
            HIDDEN, HIDDEN, PCOLS, totW);

    dim3 gg(M_TOT / 128, PROWSW / 128);   // (64, 10)
    gemm_ps_kernel<<<gg, 256, GT_SMEM>>>(xhi, xlo, whi + 0L * totW, wlo + 0L * totW,
                                         nullptr, qhi, qlo, 1);
    gemm_ps_kernel<<<gg, 256, GT_SMEM>>>(xhi, xlo, whi + 1L * totW, wlo + 1L * totW,
                                         nullptr, khi, klo, 1);
    gemm_ps_kernel<<<gg, 256, GT_SMEM>>>(xhi, xlo, whi + 2L * totW, wlo + 2L * totW,
                                         nullptr, vthi, vtlo, 3);

    flash_kernel<<<dim3(BH, S_LEN / 128), 256, FL_SMEM_BYTES>>>(
        alibi, mask, li, qhi, qlo, khi, klo, vthi, vtlo, ohi, olo);

    gemm_ps_kernel<<<gg, 256, GT_SMEM>>>((__nv_bfloat16*)ohi, (__nv_bfloat16*)olo,
                                         whi + 3L * totW, wlo + 3L * totW,
                                         out, nullptr, nullptr, 0);
}